// round 3
// baseline (speedup 1.0000x reference)
#include <cuda_runtime.h>
#include <cuda_bf16.h>

#define B_ 64
#define T_ 4096
#define N_ 32
#define D_ 64
#define LOG2PI_F 1.837877066409345f

// Scratch for emission log-probs: B*T*N floats = 33.5 MB (fits in L2).
__device__ float g_logB[(size_t)B_ * T_ * N_];

// ---------------------------------------------------------------------------
// Kernel 1: emissions. logB[b,t,n] = -0.5*(sum_d x*(x*iv - 2*mu*iv) + K_n)
// K_n = sum_d (mu^2*iv + log_var) + D*log(2pi)
// Block: 256 threads = 32 n-lanes x 8 slots, each slot handles 4 t's.
// Grid: (T/32, B).
// ---------------------------------------------------------------------------
__global__ void __launch_bounds__(256) emission_kernel(
    const float* __restrict__ X,
    const float* __restrict__ mus,
    const float* __restrict__ logvars)
{
    __shared__ float4 ivs4[16 * 32];   // [d4][n] -> iv components d4*4..d4*4+3
    __shared__ float4 ws4[16 * 32];    // w = -2*mu*iv
    __shared__ float4 Xs4[32 * 16];    // [trow][d4]
    __shared__ float  Kc[32];

    const int tid = threadIdx.x;
    const int b   = blockIdx.y;
    const int t0  = blockIdx.x * 32;

    float* ivs = reinterpret_cast<float*>(ivs4);
    float* ws  = reinterpret_cast<float*>(ws4);

    // Per-state params -> shared (layout: ((d>>2)*32 + n)*4 + (d&3))
    for (int idx = tid; idx < N_ * D_; idx += 256) {
        int n = idx >> 6;          // idx / D_
        int d = idx & 63;
        float lv = logvars[idx];
        float iv = __expf(-lv);
        int off = ((d >> 2) * 32 + n) * 4 + (d & 3);
        ivs[off] = iv;
        ws[off]  = -2.0f * mus[idx] * iv;
    }
    // X tile: 32 rows x 64 floats, contiguous
    const float4* Xv = reinterpret_cast<const float4*>(X + ((size_t)b * T_ + t0) * D_);
    for (int idx = tid; idx < 32 * 16; idx += 256) Xs4[idx] = Xv[idx];
    __syncthreads();

    if (tid < N_) {
        float k = D_ * LOG2PI_F;
        #pragma unroll 8
        for (int d = 0; d < D_; ++d) {
            float mu = mus[tid * D_ + d];
            float iv = ivs[((d >> 2) * 32 + tid) * 4 + (d & 3)];
            k += mu * mu * iv + logvars[tid * D_ + d];
        }
        Kc[tid] = k;
    }
    __syncthreads();

    const int n    = tid & 31;
    const int slot = tid >> 5;
    const int tb   = slot * 4;   // local t base (4 rows per thread)

    float acc0 = 0.f, acc1 = 0.f, acc2 = 0.f, acc3 = 0.f;
    #pragma unroll
    for (int d4 = 0; d4 < 16; ++d4) {
        float4 iv = ivs4[d4 * 32 + n];
        float4 w  = ws4[d4 * 32 + n];
        float4 x0 = Xs4[(tb + 0) * 16 + d4];
        float4 x1 = Xs4[(tb + 1) * 16 + d4];
        float4 x2 = Xs4[(tb + 2) * 16 + d4];
        float4 x3 = Xs4[(tb + 3) * 16 + d4];
        acc0 = fmaf(x0.x, fmaf(x0.x, iv.x, w.x), acc0);
        acc0 = fmaf(x0.y, fmaf(x0.y, iv.y, w.y), acc0);
        acc0 = fmaf(x0.z, fmaf(x0.z, iv.z, w.z), acc0);
        acc0 = fmaf(x0.w, fmaf(x0.w, iv.w, w.w), acc0);
        acc1 = fmaf(x1.x, fmaf(x1.x, iv.x, w.x), acc1);
        acc1 = fmaf(x1.y, fmaf(x1.y, iv.y, w.y), acc1);
        acc1 = fmaf(x1.z, fmaf(x1.z, iv.z, w.z), acc1);
        acc1 = fmaf(x1.w, fmaf(x1.w, iv.w, w.w), acc1);
        acc2 = fmaf(x2.x, fmaf(x2.x, iv.x, w.x), acc2);
        acc2 = fmaf(x2.y, fmaf(x2.y, iv.y, w.y), acc2);
        acc2 = fmaf(x2.z, fmaf(x2.z, iv.z, w.z), acc2);
        acc2 = fmaf(x2.w, fmaf(x2.w, iv.w, w.w), acc2);
        acc3 = fmaf(x3.x, fmaf(x3.x, iv.x, w.x), acc3);
        acc3 = fmaf(x3.y, fmaf(x3.y, iv.y, w.y), acc3);
        acc3 = fmaf(x3.z, fmaf(x3.z, iv.z, w.z), acc3);
        acc3 = fmaf(x3.w, fmaf(x3.w, iv.w, w.w), acc3);
    }
    float k = Kc[n];
    float* outp = g_logB + ((size_t)b * T_ + t0 + tb) * N_ + n;
    outp[0 * N_] = -0.5f * (acc0 + k);
    outp[1 * N_] = -0.5f * (acc1 + k);
    outp[2 * N_] = -0.5f * (acc2 + k);
    outp[3 * N_] = -0.5f * (acc3 + k);
}

// ---------------------------------------------------------------------------
// Kernel 2: scaled forward recursion. One warp per batch element.
// Lane j owns state j. A columns register-resident. Lag-2 renormalization so
// the warp-sum + rcp are off the loop-carried critical path.
// ---------------------------------------------------------------------------
__device__ __forceinline__ float wmax(float v) {
    #pragma unroll
    for (int o = 16; o; o >>= 1) v = fmaxf(v, __shfl_xor_sync(0xffffffffu, v, o));
    return v;
}
__device__ __forceinline__ float wsum(float v) {
    #pragma unroll
    for (int o = 16; o; o >>= 1) v += __shfl_xor_sync(0xffffffffu, v, o);
    return v;
}

__global__ void __launch_bounds__(32, 1) forward_kernel(
    const float* __restrict__ Tm,
    const float* __restrict__ priors,
    const float* __restrict__ lB,
    float* __restrict__ out)
{
    const int b = blockIdx.x;
    const int j = threadIdx.x;
    const unsigned FULL = 0xffffffffu;

    // A[i][j] = softmax(row i)[j], column j in registers
    float Acol[N_];
    #pragma unroll
    for (int i = 0; i < N_; ++i) {
        float raw = Tm[i * N_ + j];
        float mx  = wmax(raw);
        float e   = __expf(raw - mx);
        float s   = wsum(e);
        Acol[i]   = e * __frcp_rn(s);
    }

    // log pi
    float p  = priors[j];
    float pm = wmax(p);
    float pe = __expf(p - pm);
    float ps = wsum(pe);
    float lpi = (p - pm) - __logf(ps);

    const float* lbp = lB + (size_t)b * T_ * N_ + j;
    float* outb = out + (size_t)b * T_;

    // t = 0
    float a0  = lpi + lbp[0];
    float m0  = wmax(a0);
    float u   = __expf(a0 - m0);
    float sig = wsum(u);
    float ls0 = __logf(sig);
    double S  = (double)m0;                // true = u * exp(S)
    if (j == 0) outb[0] = (float)(S + (double)ls0);

    // Scale pipeline (lag-2): r_use applied this step, r_pend next rotate.
    float r_use = __frcp_rn(sig), r_pend = r_use;
    float l_use = ls0,            l_pend = ls0;

    // Emission transform pipeline: (m,e) ready for t and t+1; raw lb queue t+2,t+3.
    float lb1 = lbp[(size_t)1 * N_];
    float lb2 = lbp[(size_t)2 * N_];
    float m_cur = wmax(lb1);
    float e_cur = __expf(lb1 - m_cur);
    float m_nxt = wmax(lb2);
    float e_nxt = __expf(lb2 - m_nxt);
    float q0 = lbp[(size_t)3 * N_];
    float q1 = (4 < T_) ? lbp[(size_t)4 * N_] : 0.f;
    float er_cur = e_cur * r_use;          // emission * applied scale for t=1

    for (int t = 1; t < T_; ++t) {
        // prefetch raw logB for t+4
        float lb_new = (t + 4 < T_) ? lbp[(size_t)(t + 4) * N_] : 0.f;
        // emission transform for t+2 (latency-tolerant: used 2 iters later)
        float m2 = wmax(q0);
        float e2 = __expf(q0 - m2);

        // ---- loop-carried critical path: matvec tmp[j] = sum_i u[i]*A[i][j]
        float ac0 = 0.f, ac1 = 0.f, ac2 = 0.f, ac3 = 0.f;
        #pragma unroll
        for (int i = 0; i < N_; i += 4) {
            ac0 = fmaf(__shfl_sync(FULL, u, i + 0), Acol[i + 0], ac0);
            ac1 = fmaf(__shfl_sync(FULL, u, i + 1), Acol[i + 1], ac1);
            ac2 = fmaf(__shfl_sync(FULL, u, i + 2), Acol[i + 2], ac2);
            ac3 = fmaf(__shfl_sync(FULL, u, i + 3), Acol[i + 3], ac3);
        }
        float tmp = (ac0 + ac1) + (ac2 + ac3);
        float un  = er_cur * tmp;          // u_t (scaled by r_use, lag-2)

        // ---- bookkeeping (off critical path)
        S += (double)(m_cur) + (double)(l_use);   // S_t = S_{t-1} + m_t + log(1/rho_t)
        float sn = wsum(un);
        float lc = __logf(sn);
        if (j == 0) outb[t] = (float)(S + (double)lc);

        // rotate scale pipeline (lag-2)
        r_use = r_pend; l_use = l_pend;
        r_pend = __frcp_rn(sn); l_pend = lc;

        // rotate emission pipeline
        er_cur = e_nxt * r_use;
        m_cur = m_nxt;
        m_nxt = m2; e_nxt = e2;
        q0 = q1; q1 = lb_new;

        u = un;
    }
}

extern "C" void kernel_launch(void* const* d_in, const int* in_sizes, int n_in,
                              void* d_out, int out_size)
{
    const float* X       = (const float*)d_in[0];  // (B,T,D)
    const float* Tm      = (const float*)d_in[1];  // (N,N)
    const float* priors  = (const float*)d_in[2];  // (N,)
    const float* mus     = (const float*)d_in[3];  // (N,D)
    const float* logvars = (const float*)d_in[4];  // (N,D)
    float* outp          = (float*)d_out;          // (B,T)

    float* logB;
    cudaGetSymbolAddress((void**)&logB, g_logB);

    dim3 egrid(T_ / 32, B_);
    emission_kernel<<<egrid, 256>>>(X, mus, logvars);
    forward_kernel<<<B_, 32>>>(Tm, priors, logB, outp);
}

// round 4
// speedup vs baseline: 1.5248x; 1.5248x over previous
#include <cuda_runtime.h>
#include <cuda_bf16.h>

#define B_ 64
#define T_ 4096
#define N_ 32
#define D_ 64
#define LOG2PI_F 1.837877066409345f

// Scratch: scaled emissions E = exp(logB - M) (33.5 MB) and per-t max M (1 MB).
__device__ float g_E[(size_t)B_ * T_ * N_];
__device__ float g_M[(size_t)B_ * T_];

__device__ __forceinline__ float wmax(float v) {
    #pragma unroll
    for (int o = 16; o; o >>= 1) v = fmaxf(v, __shfl_xor_sync(0xffffffffu, v, o));
    return v;
}
__device__ __forceinline__ float wsum(float v) {
    #pragma unroll
    for (int o = 16; o; o >>= 1) v += __shfl_xor_sync(0xffffffffu, v, o);
    return v;
}

// ---------------------------------------------------------------------------
// Kernel 1: emissions, pre-transformed.
//   val[b,t,n] = -0.5*(sum_d x*(x*iv - 2*mu*iv) + K_n)
//   M[b,t] = max_n val ;  E[b,t,n] = exp(val - M)
// Block: 256 threads = 32 n-lanes x 8 warps, each thread handles 4 t's.
// Grid: (T/32, B). Warp lanes = states, so the n-max is a warp reduction.
// ---------------------------------------------------------------------------
__global__ void __launch_bounds__(256) emission_kernel(
    const float* __restrict__ X,
    const float* __restrict__ mus,
    const float* __restrict__ logvars)
{
    __shared__ float4 ivs4[16 * 32];   // [d4][n]
    __shared__ float4 ws4[16 * 32];    // w = -2*mu*iv
    __shared__ float4 Xs4[32 * 16];    // [trow][d4]
    __shared__ float  Kc[32];

    const int tid = threadIdx.x;
    const int b   = blockIdx.y;
    const int t0  = blockIdx.x * 32;

    float* ivs = reinterpret_cast<float*>(ivs4);
    float* ws  = reinterpret_cast<float*>(ws4);

    for (int idx = tid; idx < N_ * D_; idx += 256) {
        int n = idx >> 6;
        int d = idx & 63;
        float lv = logvars[idx];
        float iv = __expf(-lv);
        int off = ((d >> 2) * 32 + n) * 4 + (d & 3);
        ivs[off] = iv;
        ws[off]  = -2.0f * mus[idx] * iv;
    }
    const float4* Xv = reinterpret_cast<const float4*>(X + ((size_t)b * T_ + t0) * D_);
    for (int idx = tid; idx < 32 * 16; idx += 256) Xs4[idx] = Xv[idx];
    __syncthreads();

    if (tid < N_) {
        float k = D_ * LOG2PI_F;
        #pragma unroll 8
        for (int d = 0; d < D_; ++d) {
            float mu = mus[tid * D_ + d];
            float iv = ivs[((d >> 2) * 32 + tid) * 4 + (d & 3)];
            k += mu * mu * iv + logvars[tid * D_ + d];
        }
        Kc[tid] = k;
    }
    __syncthreads();

    const int n    = tid & 31;
    const int slot = tid >> 5;
    const int tb   = slot * 4;

    float acc0 = 0.f, acc1 = 0.f, acc2 = 0.f, acc3 = 0.f;
    #pragma unroll
    for (int d4 = 0; d4 < 16; ++d4) {
        float4 iv = ivs4[d4 * 32 + n];
        float4 w  = ws4[d4 * 32 + n];
        float4 x0 = Xs4[(tb + 0) * 16 + d4];
        float4 x1 = Xs4[(tb + 1) * 16 + d4];
        float4 x2 = Xs4[(tb + 2) * 16 + d4];
        float4 x3 = Xs4[(tb + 3) * 16 + d4];
        acc0 = fmaf(x0.x, fmaf(x0.x, iv.x, w.x), acc0);
        acc0 = fmaf(x0.y, fmaf(x0.y, iv.y, w.y), acc0);
        acc0 = fmaf(x0.z, fmaf(x0.z, iv.z, w.z), acc0);
        acc0 = fmaf(x0.w, fmaf(x0.w, iv.w, w.w), acc0);
        acc1 = fmaf(x1.x, fmaf(x1.x, iv.x, w.x), acc1);
        acc1 = fmaf(x1.y, fmaf(x1.y, iv.y, w.y), acc1);
        acc1 = fmaf(x1.z, fmaf(x1.z, iv.z, w.z), acc1);
        acc1 = fmaf(x1.w, fmaf(x1.w, iv.w, w.w), acc1);
        acc2 = fmaf(x2.x, fmaf(x2.x, iv.x, w.x), acc2);
        acc2 = fmaf(x2.y, fmaf(x2.y, iv.y, w.y), acc2);
        acc2 = fmaf(x2.z, fmaf(x2.z, iv.z, w.z), acc2);
        acc2 = fmaf(x2.w, fmaf(x2.w, iv.w, w.w), acc2);
        acc3 = fmaf(x3.x, fmaf(x3.x, iv.x, w.x), acc3);
        acc3 = fmaf(x3.y, fmaf(x3.y, iv.y, w.y), acc3);
        acc3 = fmaf(x3.z, fmaf(x3.z, iv.z, w.z), acc3);
        acc3 = fmaf(x3.w, fmaf(x3.w, iv.w, w.w), acc3);
    }
    float k = Kc[n];
    float v0 = -0.5f * (acc0 + k);
    float v1 = -0.5f * (acc1 + k);
    float v2 = -0.5f * (acc2 + k);
    float v3 = -0.5f * (acc3 + k);
    float m0 = wmax(v0), m1 = wmax(v1), m2 = wmax(v2), m3 = wmax(v3);

    const size_t tg = (size_t)b * T_ + t0 + tb;
    float* ep = g_E + tg * N_ + n;
    ep[0 * N_] = __expf(v0 - m0);
    ep[1 * N_] = __expf(v1 - m1);
    ep[2 * N_] = __expf(v2 - m2);
    ep[3 * N_] = __expf(v3 - m3);
    if (n == 0) {
        float* mp = g_M + tg;
        mp[0] = m0; mp[1] = m1; mp[2] = m2; mp[3] = m3;
    }
}

// ---------------------------------------------------------------------------
// Kernel 2: scaled forward recursion, one warp per batch element.
// Loop-carried path is ONLY the 32-state matvec (shfl+fma). Emission exp/max
// precomputed; wsum/log/rcp lag-pipelined off the critical path; loads have
// 3 iterations of slack (>> L2 latency).
// ---------------------------------------------------------------------------
__global__ void __launch_bounds__(32, 1) forward_kernel(
    const float* __restrict__ Tm,
    const float* __restrict__ priors,
    const float* __restrict__ Eb,
    const float* __restrict__ Mb,
    float* __restrict__ out)
{
    const int b = blockIdx.x;
    const int j = threadIdx.x;
    const unsigned FULL = 0xffffffffu;

    // A[i][j] = softmax(row i)[j], column j register-resident
    float Acol[N_];
    #pragma unroll
    for (int i = 0; i < N_; ++i) {
        float raw = Tm[i * N_ + j];
        float mx  = wmax(raw);
        float e   = __expf(raw - mx);
        float s   = wsum(e);
        Acol[i]   = e * __frcp_rn(s);
    }

    // pi (linear)
    float p  = priors[j];
    float pm = wmax(p);
    float pe = __expf(p - pm);
    float ps = wsum(pe);
    float pi = pe * __frcp_rn(ps);

    const float* Ep = Eb + (size_t)b * T_ * N_ + j;
    const float* Mp = Mb + (size_t)b * T_;
    float* outb = out + (size_t)b * T_;

    // t = 0:  u0 = pi * E0  (true alpha0 = u0 * exp(M0))
    float u   = pi * Ep[0];
    float sig = wsum(u);
    float ls0 = __logf(sig);
    double S  = (double)Mp[0];
    if (j == 0) outb[0] = (float)(S + (double)ls0);

    // lag-2 scale pipeline
    float r_use = __frcp_rn(sig), r_pend = r_use;
    float l_use = ls0,            l_pend = ls0;

    // emission queues: er_cur for t=1, (e_nxt,m_nxt) for t=2, eq0/eq1 for t=3,4
    float m_cur = Mp[1];
    float er_cur = Ep[(size_t)1 * N_] * r_use;
    float e_nxt = Ep[(size_t)2 * N_], m_nxt = Mp[2];
    float eq0   = Ep[(size_t)3 * N_], mq0   = Mp[3];
    float eq1   = Ep[(size_t)4 * N_], mq1   = Mp[4];

    #pragma unroll 4
    for (int t = 1; t < T_; ++t) {
        // prefetch t+4 (consumed 3 iterations later)
        float e_new = 0.f, m_new = 0.f;
        if (t + 4 < T_) {
            e_new = Ep[(size_t)(t + 4) * N_];
            m_new = Mp[t + 4];
        }

        // ---- loop-carried critical path: tmp[j] = sum_i u[i] * A[i][j]
        float ac0 = 0.f, ac1 = 0.f, ac2 = 0.f, ac3 = 0.f;
        #pragma unroll
        for (int i = 0; i < N_; i += 4) {
            ac0 = fmaf(__shfl_sync(FULL, u, i + 0), Acol[i + 0], ac0);
            ac1 = fmaf(__shfl_sync(FULL, u, i + 1), Acol[i + 1], ac1);
            ac2 = fmaf(__shfl_sync(FULL, u, i + 2), Acol[i + 2], ac2);
            ac3 = fmaf(__shfl_sync(FULL, u, i + 3), Acol[i + 3], ac3);
        }
        float tmp = (ac0 + ac1) + (ac2 + ac3);
        float un  = er_cur * tmp;

        // ---- off-critical-path bookkeeping (>= 1 full iteration of slack)
        S += (double)m_cur + (double)l_use;
        float sn = wsum(un);
        float lc = __logf(sn);
        if (j == 0) outb[t] = (float)(S + (double)lc);

        r_use = r_pend; l_use = l_pend;
        r_pend = __frcp_rn(sn); l_pend = lc;

        er_cur = e_nxt * r_use;
        m_cur  = m_nxt;
        e_nxt = eq0;  m_nxt = mq0;
        eq0   = eq1;  mq0   = mq1;
        eq1   = e_new; mq1  = m_new;

        u = un;
    }
}

extern "C" void kernel_launch(void* const* d_in, const int* in_sizes, int n_in,
                              void* d_out, int out_size)
{
    const float* X       = (const float*)d_in[0];  // (B,T,D)
    const float* Tm      = (const float*)d_in[1];  // (N,N)
    const float* priors  = (const float*)d_in[2];  // (N,)
    const float* mus     = (const float*)d_in[3];  // (N,D)
    const float* logvars = (const float*)d_in[4];  // (N,D)
    float* outp          = (float*)d_out;          // (B,T)

    float *E, *M;
    cudaGetSymbolAddress((void**)&E, g_E);
    cudaGetSymbolAddress((void**)&M, g_M);

    dim3 egrid(T_ / 32, B_);
    emission_kernel<<<egrid, 256>>>(X, mus, logvars);
    forward_kernel<<<B_, 32>>>(Tm, priors, E, M, outp);
}

// round 5
// speedup vs baseline: 1.6359x; 1.0729x over previous
#include <cuda_runtime.h>
#include <cuda_bf16.h>

#define B_ 64
#define T_ 4096
#define N_ 32
#define D_ 64
#define LOG2PI_F 1.837877066409345f
#define PAD_T 8

// Scratch: scaled emissions E = exp(logB - M), per-t max M. Padded by 8 steps
// so the forward loop's prefetch needs no bounds check (pad reads are benign).
__device__ float g_E[((size_t)B_ * T_ + PAD_T) * N_];
__device__ float g_M[(size_t)B_ * T_ + PAD_T];

__device__ __forceinline__ float wmax(float v) {
    #pragma unroll
    for (int o = 16; o; o >>= 1) v = fmaxf(v, __shfl_xor_sync(0xffffffffu, v, o));
    return v;
}
__device__ __forceinline__ float wsum(float v) {
    #pragma unroll
    for (int o = 16; o; o >>= 1) v += __shfl_xor_sync(0xffffffffu, v, o);
    return v;
}

// ---------------------------------------------------------------------------
// Kernel 1: emissions, pre-transformed.
//   val[b,t,n] = -0.5*(sum_d x*(x*iv - 2*mu*iv) + K_n)
//   M[b,t] = max_n val ;  E[b,t,n] = exp(val - M)
// ---------------------------------------------------------------------------
__global__ void __launch_bounds__(256) emission_kernel(
    const float* __restrict__ X,
    const float* __restrict__ mus,
    const float* __restrict__ logvars)
{
    __shared__ float4 ivs4[16 * 32];   // [d4][n]
    __shared__ float4 ws4[16 * 32];    // w = -2*mu*iv
    __shared__ float4 Xs4[32 * 16];    // [trow][d4]
    __shared__ float  Kc[32];

    const int tid = threadIdx.x;
    const int b   = blockIdx.y;
    const int t0  = blockIdx.x * 32;

    float* ivs = reinterpret_cast<float*>(ivs4);
    float* ws  = reinterpret_cast<float*>(ws4);

    for (int idx = tid; idx < N_ * D_; idx += 256) {
        int n = idx >> 6;
        int d = idx & 63;
        float lv = logvars[idx];
        float iv = __expf(-lv);
        int off = ((d >> 2) * 32 + n) * 4 + (d & 3);
        ivs[off] = iv;
        ws[off]  = -2.0f * mus[idx] * iv;
    }
    const float4* Xv = reinterpret_cast<const float4*>(X + ((size_t)b * T_ + t0) * D_);
    for (int idx = tid; idx < 32 * 16; idx += 256) Xs4[idx] = Xv[idx];
    __syncthreads();

    if (tid < N_) {
        float k = D_ * LOG2PI_F;
        #pragma unroll 8
        for (int d = 0; d < D_; ++d) {
            float mu = mus[tid * D_ + d];
            float iv = ivs[((d >> 2) * 32 + tid) * 4 + (d & 3)];
            k += mu * mu * iv + logvars[tid * D_ + d];
        }
        Kc[tid] = k;
    }
    __syncthreads();

    const int n    = tid & 31;
    const int slot = tid >> 5;
    const int tb   = slot * 4;

    float acc0 = 0.f, acc1 = 0.f, acc2 = 0.f, acc3 = 0.f;
    #pragma unroll
    for (int d4 = 0; d4 < 16; ++d4) {
        float4 iv = ivs4[d4 * 32 + n];
        float4 w  = ws4[d4 * 32 + n];
        float4 x0 = Xs4[(tb + 0) * 16 + d4];
        float4 x1 = Xs4[(tb + 1) * 16 + d4];
        float4 x2 = Xs4[(tb + 2) * 16 + d4];
        float4 x3 = Xs4[(tb + 3) * 16 + d4];
        acc0 = fmaf(x0.x, fmaf(x0.x, iv.x, w.x), acc0);
        acc0 = fmaf(x0.y, fmaf(x0.y, iv.y, w.y), acc0);
        acc0 = fmaf(x0.z, fmaf(x0.z, iv.z, w.z), acc0);
        acc0 = fmaf(x0.w, fmaf(x0.w, iv.w, w.w), acc0);
        acc1 = fmaf(x1.x, fmaf(x1.x, iv.x, w.x), acc1);
        acc1 = fmaf(x1.y, fmaf(x1.y, iv.y, w.y), acc1);
        acc1 = fmaf(x1.z, fmaf(x1.z, iv.z, w.z), acc1);
        acc1 = fmaf(x1.w, fmaf(x1.w, iv.w, w.w), acc1);
        acc2 = fmaf(x2.x, fmaf(x2.x, iv.x, w.x), acc2);
        acc2 = fmaf(x2.y, fmaf(x2.y, iv.y, w.y), acc2);
        acc2 = fmaf(x2.z, fmaf(x2.z, iv.z, w.z), acc2);
        acc2 = fmaf(x2.w, fmaf(x2.w, iv.w, w.w), acc2);
        acc3 = fmaf(x3.x, fmaf(x3.x, iv.x, w.x), acc3);
        acc3 = fmaf(x3.y, fmaf(x3.y, iv.y, w.y), acc3);
        acc3 = fmaf(x3.z, fmaf(x3.z, iv.z, w.z), acc3);
        acc3 = fmaf(x3.w, fmaf(x3.w, iv.w, w.w), acc3);
    }
    float k = Kc[n];
    float v0 = -0.5f * (acc0 + k);
    float v1 = -0.5f * (acc1 + k);
    float v2 = -0.5f * (acc2 + k);
    float v3 = -0.5f * (acc3 + k);
    float m0 = wmax(v0), m1 = wmax(v1), m2 = wmax(v2), m3 = wmax(v3);

    const size_t tg = (size_t)b * T_ + t0 + tb;
    float* ep = g_E + tg * N_ + n;
    ep[0 * N_] = __expf(v0 - m0);
    ep[1 * N_] = __expf(v1 - m1);
    ep[2 * N_] = __expf(v2 - m2);
    ep[3 * N_] = __expf(v3 - m3);
    if (n == 0) {
        float* mp = g_M + tg;
        mp[0] = m0; mp[1] = m1; mp[2] = m2; mp[3] = m3;
    }
}

// ---------------------------------------------------------------------------
// Kernel 2: scaled forward recursion, one warp per batch element.
// All-fp32 (no fp64 chain). Matvec: 8 accumulators (FMA depth 4 + 3-lvl tree).
// wsum/log/rcp lag-2 pipelined; prefetch distance 4, branch-free (padded E/M).
// ---------------------------------------------------------------------------
__global__ void __launch_bounds__(32, 1) forward_kernel(
    const float* __restrict__ Tm,
    const float* __restrict__ priors,
    const float* __restrict__ Eb,
    const float* __restrict__ Mb,
    float* __restrict__ out)
{
    const int b = blockIdx.x;
    const int j = threadIdx.x;
    const unsigned FULL = 0xffffffffu;

    // A[i][j] = softmax(row i)[j], column j register-resident
    float Acol[N_];
    #pragma unroll
    for (int i = 0; i < N_; ++i) {
        float raw = Tm[i * N_ + j];
        float mx  = wmax(raw);
        float e   = __expf(raw - mx);
        float s   = wsum(e);
        Acol[i]   = e * __frcp_rn(s);
    }

    // pi (linear)
    float p  = priors[j];
    float pm = wmax(p);
    float pe = __expf(p - pm);
    float ps = wsum(pe);
    float pi = pe * __frcp_rn(ps);

    const float* Ep = Eb + (size_t)b * T_ * N_ + j;
    const float* Mp = Mb + (size_t)b * T_;
    float* outb = out + (size_t)b * T_;

    // t = 0:  u0 = pi * E0  (true alpha0 = u0 * exp(M0))
    float u   = pi * Ep[0];
    float sig = wsum(u);
    float ls0 = __logf(sig);
    float S   = Mp[0];
    if (j == 0) outb[0] = S + ls0;

    // lag-2 scale pipeline
    float r_use = __frcp_rn(sig), r_pend = r_use;
    float l_use = ls0,            l_pend = ls0;

    // emission queues: er_cur for t=1, (e_nxt,m_nxt) for t=2, eq0/eq1 for t=3,4
    float m_cur = Mp[1];
    float er_cur = Ep[(size_t)1 * N_] * r_use;
    float e_nxt = Ep[(size_t)2 * N_], m_nxt = Mp[2];
    float eq0   = Ep[(size_t)3 * N_], mq0   = Mp[3];
    float eq1   = Ep[(size_t)4 * N_], mq1   = Mp[4];

    #pragma unroll 4
    for (int t = 1; t < T_; ++t) {
        // prefetch t+4 (consumed 3 iterations later; arrays padded, no branch)
        float e_new = Ep[(size_t)(t + 4) * N_];
        float m_new = Mp[t + 4];

        // ---- loop-carried critical path: tmp[j] = sum_i u[i] * A[i][j]
        float ac0 = 0.f, ac1 = 0.f, ac2 = 0.f, ac3 = 0.f;
        float ac4 = 0.f, ac5 = 0.f, ac6 = 0.f, ac7 = 0.f;
        #pragma unroll
        for (int i = 0; i < N_; i += 8) {
            ac0 = fmaf(__shfl_sync(FULL, u, i + 0), Acol[i + 0], ac0);
            ac1 = fmaf(__shfl_sync(FULL, u, i + 1), Acol[i + 1], ac1);
            ac2 = fmaf(__shfl_sync(FULL, u, i + 2), Acol[i + 2], ac2);
            ac3 = fmaf(__shfl_sync(FULL, u, i + 3), Acol[i + 3], ac3);
            ac4 = fmaf(__shfl_sync(FULL, u, i + 4), Acol[i + 4], ac4);
            ac5 = fmaf(__shfl_sync(FULL, u, i + 5), Acol[i + 5], ac5);
            ac6 = fmaf(__shfl_sync(FULL, u, i + 6), Acol[i + 6], ac6);
            ac7 = fmaf(__shfl_sync(FULL, u, i + 7), Acol[i + 7], ac7);
        }
        float tmp = ((ac0 + ac1) + (ac2 + ac3)) + ((ac4 + ac5) + (ac6 + ac7));
        float un  = er_cur * tmp;

        // ---- off-critical-path bookkeeping (lag-2: >= 2 iterations of slack)
        S += m_cur + l_use;               // fp32: abs err << 1e-3 rel tolerance
        float sn = wsum(un);
        float lc = __logf(sn);
        if (j == 0) outb[t] = S + lc;

        r_use = r_pend; l_use = l_pend;
        r_pend = __frcp_rn(sn); l_pend = lc;

        er_cur = e_nxt * r_use;
        m_cur  = m_nxt;
        e_nxt = eq0;   m_nxt = mq0;
        eq0   = eq1;   mq0   = mq1;
        eq1   = e_new; mq1   = m_new;

        u = un;
    }
}

extern "C" void kernel_launch(void* const* d_in, const int* in_sizes, int n_in,
                              void* d_out, int out_size)
{
    const float* X       = (const float*)d_in[0];  // (B,T,D)
    const float* Tm      = (const float*)d_in[1];  // (N,N)
    const float* priors  = (const float*)d_in[2];  // (N,)
    const float* mus     = (const float*)d_in[3];  // (N,D)
    const float* logvars = (const float*)d_in[4];  // (N,D)
    float* outp          = (float*)d_out;          // (B,T)

    float *E, *M;
    cudaGetSymbolAddress((void**)&E, g_E);
    cudaGetSymbolAddress((void**)&M, g_M);

    dim3 egrid(T_ / 32, B_);
    emission_kernel<<<egrid, 256>>>(X, mus, logvars);
    forward_kernel<<<B_, 32>>>(Tm, priors, E, M, outp);
}

// round 7
// speedup vs baseline: 1.8189x; 1.1119x over previous
#include <cuda_runtime.h>
#include <cuda_bf16.h>

#define B_ 64
#define T_ 4096
#define N_ 32
#define D_ 64
#define LOG2PI_F 1.837877066409345f
#define PAD_T 8

// Scratch: scaled emissions E = exp(logB - M), per-t max M. Padded so the
// forward loop prefetch needs no bounds check.
__device__ float g_E[((size_t)B_ * T_ + PAD_T) * N_];
__device__ float g_M[(size_t)B_ * T_ + PAD_T];

__device__ __forceinline__ float wmax(float v) {
    #pragma unroll
    for (int o = 16; o; o >>= 1) v = fmaxf(v, __shfl_xor_sync(0xffffffffu, v, o));
    return v;
}
__device__ __forceinline__ float wsum(float v) {
    #pragma unroll
    for (int o = 16; o; o >>= 1) v += __shfl_xor_sync(0xffffffffu, v, o);
    return v;
}

// ---------------------------------------------------------------------------
// Kernel 1: emissions (same as R5, which passed at rel_err 1.9e-6).
//   val[b,t,n] = -0.5*(sum_d x*(x*iv - 2*mu*iv) + K_n)
//   M[b,t] = max_n val ;  E[b,t,n] = exp(val - M)
// ---------------------------------------------------------------------------
__global__ void __launch_bounds__(256) emission_kernel(
    const float* __restrict__ X,
    const float* __restrict__ mus,
    const float* __restrict__ logvars)
{
    __shared__ float4 ivs4[16 * 32];
    __shared__ float4 ws4[16 * 32];
    __shared__ float4 Xs4[32 * 16];
    __shared__ float  Kc[32];

    const int tid = threadIdx.x;
    const int b   = blockIdx.y;
    const int t0  = blockIdx.x * 32;

    float* ivs = reinterpret_cast<float*>(ivs4);
    float* ws  = reinterpret_cast<float*>(ws4);

    for (int idx = tid; idx < N_ * D_; idx += 256) {
        int n = idx >> 6;
        int d = idx & 63;
        float lv = logvars[idx];
        float iv = __expf(-lv);
        int off = ((d >> 2) * 32 + n) * 4 + (d & 3);
        ivs[off] = iv;
        ws[off]  = -2.0f * mus[idx] * iv;
    }
    const float4* Xv = reinterpret_cast<const float4*>(X + ((size_t)b * T_ + t0) * D_);
    for (int idx = tid; idx < 32 * 16; idx += 256) Xs4[idx] = Xv[idx];
    __syncthreads();

    if (tid < N_) {
        float k = D_ * LOG2PI_F;
        #pragma unroll 8
        for (int d = 0; d < D_; ++d) {
            float mu = mus[tid * D_ + d];
            float iv = ivs[((d >> 2) * 32 + tid) * 4 + (d & 3)];
            k += mu * mu * iv + logvars[tid * D_ + d];
        }
        Kc[tid] = k;
    }
    __syncthreads();

    const int n    = tid & 31;
    const int slot = tid >> 5;
    const int tb   = slot * 4;

    float acc0 = 0.f, acc1 = 0.f, acc2 = 0.f, acc3 = 0.f;
    #pragma unroll
    for (int d4 = 0; d4 < 16; ++d4) {
        float4 iv = ivs4[d4 * 32 + n];
        float4 w  = ws4[d4 * 32 + n];
        float4 x0 = Xs4[(tb + 0) * 16 + d4];
        float4 x1 = Xs4[(tb + 1) * 16 + d4];
        float4 x2 = Xs4[(tb + 2) * 16 + d4];
        float4 x3 = Xs4[(tb + 3) * 16 + d4];
        acc0 = fmaf(x0.x, fmaf(x0.x, iv.x, w.x), acc0);
        acc0 = fmaf(x0.y, fmaf(x0.y, iv.y, w.y), acc0);
        acc0 = fmaf(x0.z, fmaf(x0.z, iv.z, w.z), acc0);
        acc0 = fmaf(x0.w, fmaf(x0.w, iv.w, w.w), acc0);
        acc1 = fmaf(x1.x, fmaf(x1.x, iv.x, w.x), acc1);
        acc1 = fmaf(x1.y, fmaf(x1.y, iv.y, w.y), acc1);
        acc1 = fmaf(x1.z, fmaf(x1.z, iv.z, w.z), acc1);
        acc1 = fmaf(x1.w, fmaf(x1.w, iv.w, w.w), acc1);
        acc2 = fmaf(x2.x, fmaf(x2.x, iv.x, w.x), acc2);
        acc2 = fmaf(x2.y, fmaf(x2.y, iv.y, w.y), acc2);
        acc2 = fmaf(x2.z, fmaf(x2.z, iv.z, w.z), acc2);
        acc2 = fmaf(x2.w, fmaf(x2.w, iv.w, w.w), acc2);
        acc3 = fmaf(x3.x, fmaf(x3.x, iv.x, w.x), acc3);
        acc3 = fmaf(x3.y, fmaf(x3.y, iv.y, w.y), acc3);
        acc3 = fmaf(x3.z, fmaf(x3.z, iv.z, w.z), acc3);
        acc3 = fmaf(x3.w, fmaf(x3.w, iv.w, w.w), acc3);
    }
    float k = Kc[n];
    float v0 = -0.5f * (acc0 + k);
    float v1 = -0.5f * (acc1 + k);
    float v2 = -0.5f * (acc2 + k);
    float v3 = -0.5f * (acc3 + k);
    float m0 = wmax(v0), m1 = wmax(v1), m2 = wmax(v2), m3 = wmax(v3);

    const size_t tg = (size_t)b * T_ + t0 + tb;
    float* ep = g_E + tg * N_ + n;
    ep[0 * N_] = __expf(v0 - m0);
    ep[1 * N_] = __expf(v1 - m1);
    ep[2 * N_] = __expf(v2 - m2);
    ep[3 * N_] = __expf(v3 - m3);
    if (n == 0) {
        float* mp = g_M + tg;
        mp[0] = m0; mp[1] = m1; mp[2] = m2; mp[3] = m3;
    }
}

// ---------------------------------------------------------------------------
// Kernel 2: forward recursion, lag-1 normalization with the butterfly sum
// OVERLAPPED against the matvec. Both the 5-level sum of u_{t-1} and the 32
// matvec shfls depend only on u_{t-1}, so the serial butterfly chain hides
// under the matvec's independent instruction stream. u_t = (e_t*tmp)*rcp(sig)
// -> sum(u_t) in [~0.02, 1] every step (A is strongly mixing): stable, exact
// bookkeeping (every applied scale is logged into S).
//   out[t-1] = S_{t-1} + log(sigma_{t-1})   (written during iteration t)
//   S_t      = S_{t-1} + m_t + log(sigma_{t-1})
// ---------------------------------------------------------------------------
__global__ void __launch_bounds__(32, 1) forward_kernel(
    const float* __restrict__ Tm,
    const float* __restrict__ priors,
    const float* __restrict__ Eb,
    const float* __restrict__ Mb,
    float* __restrict__ out)
{
    const int b = blockIdx.x;
    const int j = threadIdx.x;
    const unsigned FULL = 0xffffffffu;

    // A[i][j] = softmax(row i)[j], column j register-resident
    float Acol[N_];
    #pragma unroll
    for (int i = 0; i < N_; ++i) {
        float raw = Tm[i * N_ + j];
        float mx  = wmax(raw);
        float e   = __expf(raw - mx);
        float s   = wsum(e);
        Acol[i]   = e * __frcp_rn(s);
    }

    // pi (linear, normalized once)
    float p  = priors[j];
    float pm = wmax(p);
    float pe = __expf(p - pm);
    float ps = wsum(pe);
    float pi = pe * __frcp_rn(ps);

    const float* Ep = Eb + (size_t)b * T_ * N_ + j;
    const float* Mp = Mb + (size_t)b * T_;
    float* outb = out + (size_t)b * T_;

    // u_0 (unnormalized; sum in [~0.02,1]); alpha_0 = u_0 * exp(S)
    float u = pi * Ep[0];
    float S = Mp[0];

    // emission queues (prefetch distance 4; arrays padded -> branch-free)
    float m_cur = Mp[1];
    float er_cur = Ep[(size_t)1 * N_];
    float e_q1 = Ep[(size_t)2 * N_], m_q1 = Mp[2];
    float e_q2 = Ep[(size_t)3 * N_], m_q2 = Mp[3];
    float e_q3 = Ep[(size_t)4 * N_], m_q3 = Mp[4];

    #pragma unroll 4
    for (int t = 1; t < T_; ++t) {
        float e_new = Ep[(size_t)(t + 4) * N_];
        float m_new = Mp[t + 4];

        // ---- butterfly sum of u_{t-1} (serial chain, overlapped w/ matvec)
        float s1 = u  + __shfl_xor_sync(FULL, u,  16);
        float s2 = s1 + __shfl_xor_sync(FULL, s1, 8);
        float s3 = s2 + __shfl_xor_sync(FULL, s2, 4);
        float s4 = s3 + __shfl_xor_sync(FULL, s3, 2);
        float sig = s4 + __shfl_xor_sync(FULL, s4, 1);

        // ---- matvec: tmp[j] = sum_i u[i] * A[i][j] (independent of butterfly)
        float ac0 = 0.f, ac1 = 0.f, ac2 = 0.f, ac3 = 0.f;
        float ac4 = 0.f, ac5 = 0.f, ac6 = 0.f, ac7 = 0.f;
        #pragma unroll
        for (int i = 0; i < N_; i += 8) {
            ac0 = fmaf(__shfl_sync(FULL, u, i + 0), Acol[i + 0], ac0);
            ac1 = fmaf(__shfl_sync(FULL, u, i + 1), Acol[i + 1], ac1);
            ac2 = fmaf(__shfl_sync(FULL, u, i + 2), Acol[i + 2], ac2);
            ac3 = fmaf(__shfl_sync(FULL, u, i + 3), Acol[i + 3], ac3);
            ac4 = fmaf(__shfl_sync(FULL, u, i + 4), Acol[i + 4], ac4);
            ac5 = fmaf(__shfl_sync(FULL, u, i + 5), Acol[i + 5], ac5);
            ac6 = fmaf(__shfl_sync(FULL, u, i + 6), Acol[i + 6], ac6);
            ac7 = fmaf(__shfl_sync(FULL, u, i + 7), Acol[i + 7], ac7);
        }
        float tmp = ((ac0 + ac1) + (ac2 + ac3)) + ((ac4 + ac5) + (ac6 + ac7));

        // ---- outputs & scale (lsig/store off the carried path)
        float lsig = __logf(sig);
        if (j == 0) outb[t - 1] = S + lsig;
        S += m_cur + lsig;

        float r = __frcp_rn(sig);
        float x = er_cur * tmp;
        u = x * r;                       // u_t, sum in [~0.02, 1]

        // rotate queues
        er_cur = e_q1;  m_cur = m_q1;
        e_q1 = e_q2;    m_q1 = m_q2;
        e_q2 = e_q3;    m_q2 = m_q3;
        e_q3 = e_new;   m_q3 = m_new;
    }

    // epilogue: out[T-1]
    float sigF = wsum(u);
    if (j == 0) outb[T_ - 1] = S + __logf(sigF);
}

extern "C" void kernel_launch(void* const* d_in, const int* in_sizes, int n_in,
                              void* d_out, int out_size)
{
    const float* X       = (const float*)d_in[0];  // (B,T,D)
    const float* Tm      = (const float*)d_in[1];  // (N,N)
    const float* priors  = (const float*)d_in[2];  // (N,)
    const float* mus     = (const float*)d_in[3];  // (N,D)
    const float* logvars = (const float*)d_in[4];  // (N,D)
    float* outp          = (float*)d_out;          // (B,T)

    float *E, *M;
    cudaGetSymbolAddress((void**)&E, g_E);
    cudaGetSymbolAddress((void**)&M, g_M);

    dim3 egrid(T_ / 32, B_);
    emission_kernel<<<egrid, 256>>>(X, mus, logvars);
    forward_kernel<<<B_, 32>>>(Tm, priors, E, M, outp);
}

// round 10
// speedup vs baseline: 2.0087x; 1.1044x over previous
#include <cuda_runtime.h>
#include <cuda_bf16.h>

#define B_ 64
#define T_ 4096
#define N_ 32
#define D_ 64
#define LOG2PI_F 1.837877066409345f
#define PAD_T 8

// Scratch: scaled emissions E = exp(logB - M), per-t max M. Padded so the
// forward loop prefetch needs no bounds check.
__device__ float g_E[((size_t)B_ * T_ + PAD_T) * N_];
__device__ float g_M[(size_t)B_ * T_ + PAD_T];

__device__ __forceinline__ float wmax(float v) {
    #pragma unroll
    for (int o = 16; o; o >>= 1) v = fmaxf(v, __shfl_xor_sync(0xffffffffu, v, o));
    return v;
}
__device__ __forceinline__ float wsum(float v) {
    #pragma unroll
    for (int o = 16; o; o >>= 1) v += __shfl_xor_sync(0xffffffffu, v, o);
    return v;
}

// ---------------------------------------------------------------------------
// Kernel 1: emissions. Tile = 64 timesteps per block (amortizes per-block
// parameter setup 2x vs 32). 256 threads = 32 n-lanes x 8 slots; each thread
// produces 8 timesteps.
//   val[b,t,n] = -0.5*(sum_d x*(x*iv - 2*mu*iv) + K_n)
//   M[b,t] = max_n val ;  E[b,t,n] = exp(val - M)
// ---------------------------------------------------------------------------
#define TILE_T 64
#define ROWS_PT 8   // TILE_T / 8 slots

__global__ void __launch_bounds__(256) emission_kernel(
    const float* __restrict__ X,
    const float* __restrict__ mus,
    const float* __restrict__ logvars)
{
    __shared__ float4 ivs4[16 * 32];          // [d4][n]
    __shared__ float4 ws4[16 * 32];           // w = -2*mu*iv
    __shared__ float4 Xs4[TILE_T * 16];       // [trow][d4]
    __shared__ float  Kc[32];

    const int tid = threadIdx.x;
    const int b   = blockIdx.y;
    const int t0  = blockIdx.x * TILE_T;

    float* ivs = reinterpret_cast<float*>(ivs4);
    float* ws  = reinterpret_cast<float*>(ws4);

    for (int idx = tid; idx < N_ * D_; idx += 256) {
        int n = idx >> 6;
        int d = idx & 63;
        float lv = logvars[idx];
        float iv = __expf(-lv);
        int off = ((d >> 2) * 32 + n) * 4 + (d & 3);
        ivs[off] = iv;
        ws[off]  = -2.0f * mus[idx] * iv;
    }
    const float4* Xv = reinterpret_cast<const float4*>(X + ((size_t)b * T_ + t0) * D_);
    for (int idx = tid; idx < TILE_T * 16; idx += 256) Xs4[idx] = Xv[idx];
    __syncthreads();

    if (tid < N_) {
        float k = D_ * LOG2PI_F;
        #pragma unroll 8
        for (int d = 0; d < D_; ++d) {
            float mu = mus[tid * D_ + d];
            float iv = ivs[((d >> 2) * 32 + tid) * 4 + (d & 3)];
            k += mu * mu * iv + logvars[tid * D_ + d];
        }
        Kc[tid] = k;
    }
    __syncthreads();

    const int n    = tid & 31;
    const int slot = tid >> 5;
    const int tb   = slot * ROWS_PT;

    float acc[ROWS_PT];
    #pragma unroll
    for (int r = 0; r < ROWS_PT; ++r) acc[r] = 0.f;

    #pragma unroll
    for (int d4 = 0; d4 < 16; ++d4) {
        float4 iv = ivs4[d4 * 32 + n];
        float4 w  = ws4[d4 * 32 + n];
        #pragma unroll
        for (int r = 0; r < ROWS_PT; ++r) {
            float4 x = Xs4[(tb + r) * 16 + d4];
            float a = acc[r];
            a = fmaf(x.x, fmaf(x.x, iv.x, w.x), a);
            a = fmaf(x.y, fmaf(x.y, iv.y, w.y), a);
            a = fmaf(x.z, fmaf(x.z, iv.z, w.z), a);
            a = fmaf(x.w, fmaf(x.w, iv.w, w.w), a);
            acc[r] = a;
        }
    }
    const float k = Kc[n];
    const size_t tg = (size_t)b * T_ + t0 + tb;
    float* ep = g_E + tg * N_ + n;
    float* mp = g_M + tg;
    #pragma unroll
    for (int r = 0; r < ROWS_PT; ++r) {
        float v = -0.5f * (acc[r] + k);
        float m = wmax(v);
        ep[(size_t)r * N_] = __expf(v - m);
        if (n == 0) mp[r] = m;
    }
}

// ---------------------------------------------------------------------------
// Kernel 2: forward recursion, lag-1 normalization. The warp sum sigma =
// sum(u) is built as an FADD TREE over the SAME broadcast registers the
// matvec already produces (shfl(u,i)) -- no butterfly, no extra shfl
// latency. Exact bookkeeping (R7 semantics):
//   sigma = sum(u_{t-1});  out[t-1] = S_{t-1} + log sigma
//   S_t = S_{t-1} + m_t + log sigma;  u_t = (e_t * A^T u_{t-1}) * rcp(sigma)
// ---------------------------------------------------------------------------
__global__ void __launch_bounds__(32, 1) forward_kernel(
    const float* __restrict__ Tm,
    const float* __restrict__ priors,
    const float* __restrict__ Eb,
    const float* __restrict__ Mb,
    float* __restrict__ out)
{
    const int b = blockIdx.x;
    const int j = threadIdx.x;
    const unsigned FULL = 0xffffffffu;

    // A[i][j] = softmax(row i)[j], column j register-resident
    float Acol[N_];
    #pragma unroll
    for (int i = 0; i < N_; ++i) {
        float raw = Tm[i * N_ + j];
        float mx  = wmax(raw);
        float e   = __expf(raw - mx);
        float s   = wsum(e);
        Acol[i]   = e * __frcp_rn(s);
    }

    // pi (linear, normalized once)
    float p  = priors[j];
    float pm = wmax(p);
    float pe = __expf(p - pm);
    float ps = wsum(pe);
    float pi = pe * __frcp_rn(ps);

    const float* Ep = Eb + (size_t)b * T_ * N_ + j;
    const float* Mp = Mb + (size_t)b * T_;
    float* outb = out + (size_t)b * T_;

    // u_0 (unnormalized); alpha_0 = u_0 * exp(S)
    float u = pi * Ep[0];
    float S = Mp[0];

    // emission queues (prefetch distance 4; arrays padded -> branch-free)
    float m_cur = Mp[1];
    float er_cur = Ep[(size_t)1 * N_];
    float e_q1 = Ep[(size_t)2 * N_], m_q1 = Mp[2];
    float e_q2 = Ep[(size_t)3 * N_], m_q2 = Mp[3];
    float e_q3 = Ep[(size_t)4 * N_], m_q3 = Mp[4];

    #pragma unroll 4
    for (int t = 1; t < T_; ++t) {
        float e_new = Ep[(size_t)(t + 4) * N_];
        float m_new = Mp[t + 4];

        // ---- broadcasts of u_{t-1} (needed by matvec anyway)
        float b0  = __shfl_sync(FULL, u, 0),  b1  = __shfl_sync(FULL, u, 1);
        float b2  = __shfl_sync(FULL, u, 2),  b3  = __shfl_sync(FULL, u, 3);
        float b4  = __shfl_sync(FULL, u, 4),  b5  = __shfl_sync(FULL, u, 5);
        float b6  = __shfl_sync(FULL, u, 6),  b7  = __shfl_sync(FULL, u, 7);
        float b8  = __shfl_sync(FULL, u, 8),  b9  = __shfl_sync(FULL, u, 9);
        float b10 = __shfl_sync(FULL, u, 10), b11 = __shfl_sync(FULL, u, 11);
        float b12 = __shfl_sync(FULL, u, 12), b13 = __shfl_sync(FULL, u, 13);
        float b14 = __shfl_sync(FULL, u, 14), b15 = __shfl_sync(FULL, u, 15);
        float b16 = __shfl_sync(FULL, u, 16), b17 = __shfl_sync(FULL, u, 17);
        float b18 = __shfl_sync(FULL, u, 18), b19 = __shfl_sync(FULL, u, 19);
        float b20 = __shfl_sync(FULL, u, 20), b21 = __shfl_sync(FULL, u, 21);
        float b22 = __shfl_sync(FULL, u, 22), b23 = __shfl_sync(FULL, u, 23);
        float b24 = __shfl_sync(FULL, u, 24), b25 = __shfl_sync(FULL, u, 25);
        float b26 = __shfl_sync(FULL, u, 26), b27 = __shfl_sync(FULL, u, 27);
        float b28 = __shfl_sync(FULL, u, 28), b29 = __shfl_sync(FULL, u, 29);
        float b30 = __shfl_sync(FULL, u, 30), b31 = __shfl_sync(FULL, u, 31);

        // ---- sigma = sum(u_{t-1}): FADD tree over the broadcasts (no shfl)
        float t0a = (b0 + b1)   + (b2 + b3);
        float t1a = (b4 + b5)   + (b6 + b7);
        float t2a = (b8 + b9)   + (b10 + b11);
        float t3a = (b12 + b13) + (b14 + b15);
        float t4a = (b16 + b17) + (b18 + b19);
        float t5a = (b20 + b21) + (b22 + b23);
        float t6a = (b24 + b25) + (b26 + b27);
        float t7a = (b28 + b29) + (b30 + b31);
        float sig = ((t0a + t1a) + (t2a + t3a)) + ((t4a + t5a) + (t6a + t7a));

        // ---- matvec: tmp[j] = sum_i u[i] * A[i][j]
        float ac0 = fmaf(b0, Acol[0],  fmaf(b1, Acol[1],  fmaf(b2, Acol[2],  b3 * Acol[3])));
        float ac1 = fmaf(b4, Acol[4],  fmaf(b5, Acol[5],  fmaf(b6, Acol[6],  b7 * Acol[7])));
        float ac2 = fmaf(b8, Acol[8],  fmaf(b9, Acol[9],  fmaf(b10, Acol[10], b11 * Acol[11])));
        float ac3 = fmaf(b12, Acol[12], fmaf(b13, Acol[13], fmaf(b14, Acol[14], b15 * Acol[15])));
        float ac4 = fmaf(b16, Acol[16], fmaf(b17, Acol[17], fmaf(b18, Acol[18], b19 * Acol[19])));
        float ac5 = fmaf(b20, Acol[20], fmaf(b21, Acol[21], fmaf(b22, Acol[22], b23 * Acol[23])));
        float ac6 = fmaf(b24, Acol[24], fmaf(b25, Acol[25], fmaf(b26, Acol[26], b27 * Acol[27])));
        float ac7 = fmaf(b28, Acol[28], fmaf(b29, Acol[29], fmaf(b30, Acol[30], b31 * Acol[31])));
        float tmp = ((ac0 + ac1) + (ac2 + ac3)) + ((ac4 + ac5) + (ac6 + ac7));

        // ---- scale + outputs (log/store off the carried path)
        float r = __frcp_rn(sig);
        float lsig = __logf(sig);
        if (j == 0) outb[t - 1] = S + lsig;
        S += m_cur + lsig;

        u = (er_cur * tmp) * r;          // u_t

        // rotate queues
        er_cur = e_q1;  m_cur = m_q1;
        e_q1 = e_q2;    m_q1 = m_q2;
        e_q2 = e_q3;    m_q2 = m_q3;
        e_q3 = e_new;   m_q3 = m_new;
    }

    // epilogue: out[T-1]
    float sigF = wsum(u);
    if (j == 0) outb[T_ - 1] = S + __logf(sigF);
}

extern "C" void kernel_launch(void* const* d_in, const int* in_sizes, int n_in,
                              void* d_out, int out_size)
{
    const float* X       = (const float*)d_in[0];  // (B,T,D)
    const float* Tm      = (const float*)d_in[1];  // (N,N)
    const float* priors  = (const float*)d_in[2];  // (N,)
    const float* mus     = (const float*)d_in[3];  // (N,D)
    const float* logvars = (const float*)d_in[4];  // (N,D)
    float* outp          = (float*)d_out;          // (B,T)

    float *E, *M;
    cudaGetSymbolAddress((void**)&E, g_E);
    cudaGetSymbolAddress((void**)&M, g_M);

    dim3 egrid(T_ / TILE_T, B_);
    emission_kernel<<<egrid, 256>>>(X, mus, logvars);
    forward_kernel<<<B_, 32>>>(Tm, priors, E, M, outp);
}

// round 11
// speedup vs baseline: 2.1585x; 1.0745x over previous
#include <cuda_runtime.h>
#include <cuda_bf16.h>

#define B_ 64
#define T_ 4096
#define N_ 32
#define D_ 64
#define LOG2PI_F 1.837877066409345f
#define PAD_T 8

// Scratch: scaled emissions E = exp(logB - M), per-t max M. Padded so the
// forward loop prefetch needs no bounds check.
__device__ float g_E[((size_t)B_ * T_ + PAD_T) * N_];
__device__ float g_M[(size_t)B_ * T_ + PAD_T];

__device__ __forceinline__ float wmax(float v) {
    #pragma unroll
    for (int o = 16; o; o >>= 1) v = fmaxf(v, __shfl_xor_sync(0xffffffffu, v, o));
    return v;
}
__device__ __forceinline__ float wsum(float v) {
    #pragma unroll
    for (int o = 16; o; o >>= 1) v += __shfl_xor_sync(0xffffffffu, v, o);
    return v;
}

// ---- packed f32x2 helpers (PTX ISA 8.6, sm_100 base target) ----
__device__ __forceinline__ unsigned long long ffma2(
    unsigned long long a, unsigned long long b, unsigned long long c) {
    unsigned long long d;
    asm("fma.rn.f32x2 %0, %1, %2, %3;" : "=l"(d) : "l"(a), "l"(b), "l"(c));
    return d;
}
__device__ __forceinline__ unsigned long long fadd2(
    unsigned long long a, unsigned long long b) {
    unsigned long long d;
    asm("add.rn.f32x2 %0, %1, %2;" : "=l"(d) : "l"(a), "l"(b));
    return d;
}
__device__ __forceinline__ unsigned long long pack2(float lo, float hi) {
    unsigned long long d;
    asm("mov.b64 %0, {%1, %2};" : "=l"(d) : "f"(lo), "f"(hi));
    return d;
}
__device__ __forceinline__ void unpack2(unsigned long long v, float& lo, float& hi) {
    asm("mov.b64 {%0, %1}, %2;" : "=f"(lo), "=f"(hi) : "l"(v));
}

// ---------------------------------------------------------------------------
// Kernel 1: emissions. Tile = 64 timesteps/block; 256 threads = 32 n-lanes x
// 8 slots; each thread produces 8 timesteps.
//   val[b,t,n] = -0.5*(sum_d x*(x*iv - 2*mu*iv) + K_n)
//   M[b,t] = max_n val ;  E[b,t,n] = exp(val - M)
// ---------------------------------------------------------------------------
#define TILE_T 64
#define ROWS_PT 8

__global__ void __launch_bounds__(256) emission_kernel(
    const float* __restrict__ X,
    const float* __restrict__ mus,
    const float* __restrict__ logvars)
{
    __shared__ float4 ivs4[16 * 32];
    __shared__ float4 ws4[16 * 32];
    __shared__ float4 Xs4[TILE_T * 16];
    __shared__ float  Kc[32];

    const int tid = threadIdx.x;
    const int b   = blockIdx.y;
    const int t0  = blockIdx.x * TILE_T;

    float* ivs = reinterpret_cast<float*>(ivs4);
    float* ws  = reinterpret_cast<float*>(ws4);

    for (int idx = tid; idx < N_ * D_; idx += 256) {
        int n = idx >> 6;
        int d = idx & 63;
        float lv = logvars[idx];
        float iv = __expf(-lv);
        int off = ((d >> 2) * 32 + n) * 4 + (d & 3);
        ivs[off] = iv;
        ws[off]  = -2.0f * mus[idx] * iv;
    }
    const float4* Xv = reinterpret_cast<const float4*>(X + ((size_t)b * T_ + t0) * D_);
    for (int idx = tid; idx < TILE_T * 16; idx += 256) Xs4[idx] = Xv[idx];
    __syncthreads();

    if (tid < N_) {
        float k = D_ * LOG2PI_F;
        #pragma unroll 8
        for (int d = 0; d < D_; ++d) {
            float mu = mus[tid * D_ + d];
            float iv = ivs[((d >> 2) * 32 + tid) * 4 + (d & 3)];
            k += mu * mu * iv + logvars[tid * D_ + d];
        }
        Kc[tid] = k;
    }
    __syncthreads();

    const int n    = tid & 31;
    const int slot = tid >> 5;
    const int tb   = slot * ROWS_PT;

    float acc[ROWS_PT];
    #pragma unroll
    for (int r = 0; r < ROWS_PT; ++r) acc[r] = 0.f;

    #pragma unroll
    for (int d4 = 0; d4 < 16; ++d4) {
        float4 iv = ivs4[d4 * 32 + n];
        float4 w  = ws4[d4 * 32 + n];
        #pragma unroll
        for (int r = 0; r < ROWS_PT; ++r) {
            float4 x = Xs4[(tb + r) * 16 + d4];
            float a = acc[r];
            a = fmaf(x.x, fmaf(x.x, iv.x, w.x), a);
            a = fmaf(x.y, fmaf(x.y, iv.y, w.y), a);
            a = fmaf(x.z, fmaf(x.z, iv.z, w.z), a);
            a = fmaf(x.w, fmaf(x.w, iv.w, w.w), a);
            acc[r] = a;
        }
    }
    const float k = Kc[n];
    const size_t tg = (size_t)b * T_ + t0 + tb;
    float* ep = g_E + tg * N_ + n;
    float* mp = g_M + tg;
    #pragma unroll
    for (int r = 0; r < ROWS_PT; ++r) {
        float v = -0.5f * (acc[r] + k);
        float m = wmax(v);
        ep[(size_t)r * N_] = __expf(v - m);
        if (n == 0) mp[r] = m;
    }
}

// ---------------------------------------------------------------------------
// Kernel 2: forward recursion, lag-1 normalization (R10 semantics, exact
// bookkeeping). Broadcast via SHARED MEMORY instead of 32 SHFLs: STS u,
// __syncwarp, 8x LDS.128 (broadcast reads, conflict-free). Matvec and sigma
// computed with packed f32x2 FMA/ADD (half the issue count). Double-buffered
// u slot -> one syncwarp per iteration.
//   sigma = sum(u_{t-1});  out[t-1] = S_{t-1} + log sigma
//   S_t = S_{t-1} + m_t + log sigma;  u_t = (e_t * A^T u_{t-1}) * rcp(sigma)
// ---------------------------------------------------------------------------
__global__ void __launch_bounds__(32, 1) forward_kernel(
    const float* __restrict__ Tm,
    const float* __restrict__ priors,
    const float* __restrict__ Eb,
    const float* __restrict__ Mb,
    float* __restrict__ out)
{
    __shared__ __align__(16) float ubuf[2][N_];

    const int b = blockIdx.x;
    const int j = threadIdx.x;

    // A[i][j] = softmax(row i)[j]; pack column j into 16 f32x2 pairs:
    // A2[p] = (A[2p][j], A[2p+1][j])
    float Acol[N_];
    #pragma unroll
    for (int i = 0; i < N_; ++i) {
        float raw = Tm[i * N_ + j];
        float mx  = wmax(raw);
        float e   = __expf(raw - mx);
        float s   = wsum(e);
        Acol[i]   = e * __frcp_rn(s);
    }
    unsigned long long A2[N_ / 2];
    #pragma unroll
    for (int p = 0; p < N_ / 2; ++p) A2[p] = pack2(Acol[2 * p], Acol[2 * p + 1]);

    // pi (linear, normalized once)
    float p  = priors[j];
    float pm = wmax(p);
    float pe = __expf(p - pm);
    float ps = wsum(pe);
    float pi = pe * __frcp_rn(ps);

    const float* Ep = Eb + (size_t)b * T_ * N_ + j;
    const float* Mp = Mb + (size_t)b * T_;
    float* outb = out + (size_t)b * T_;

    // u_0 (unnormalized); alpha_0 = u_0 * exp(S)
    float u = pi * Ep[0];
    float S = Mp[0];

    // emission queues (prefetch distance 4; arrays padded -> branch-free)
    float m_cur = Mp[1];
    float er_cur = Ep[(size_t)1 * N_];
    float e_q1 = Ep[(size_t)2 * N_], m_q1 = Mp[2];
    float e_q2 = Ep[(size_t)3 * N_], m_q2 = Mp[3];
    float e_q3 = Ep[(size_t)4 * N_], m_q3 = Mp[4];

    #pragma unroll 4
    for (int t = 1; t < T_; ++t) {
        float e_new = Ep[(size_t)(t + 4) * N_];
        float m_new = Mp[t + 4];

        // ---- publish u_{t-1}, then broadcast-read it as 8 x 16B
        const int buf = t & 1;
        ubuf[buf][j] = u;
        __syncwarp();
        const ulonglong2* uv = reinterpret_cast<const ulonglong2*>(ubuf[buf]);
        ulonglong2 q0 = uv[0], q1 = uv[1], q2 = uv[2], q3 = uv[3];
        ulonglong2 q4 = uv[4], q5 = uv[5], q6 = uv[6], q7 = uv[7];

        // ---- matvec (packed): tmp[j] = sum_p pair_p(u) . A2[p]
        unsigned long long c0, c1, c2, c3;
        c0 = ffma2(q0.x, A2[0], ffma2(q0.y, A2[1], 0ull));
        c1 = ffma2(q1.x, A2[2], ffma2(q1.y, A2[3], 0ull));
        c2 = ffma2(q2.x, A2[4], ffma2(q2.y, A2[5], 0ull));
        c3 = ffma2(q3.x, A2[6], ffma2(q3.y, A2[7], 0ull));
        c0 = ffma2(q4.x, A2[8],  ffma2(q4.y, A2[9],  c0));
        c1 = ffma2(q5.x, A2[10], ffma2(q5.y, A2[11], c1));
        c2 = ffma2(q6.x, A2[12], ffma2(q6.y, A2[13], c2));
        c3 = ffma2(q7.x, A2[14], ffma2(q7.y, A2[15], c3));
        unsigned long long cs = fadd2(fadd2(c0, c1), fadd2(c2, c3));
        float clo, chi;
        unpack2(cs, clo, chi);
        float tmp = clo + chi;

        // ---- sigma = sum(u_{t-1}) (packed tree over the same loads)
        unsigned long long s0 = fadd2(fadd2(q0.x, q0.y), fadd2(q1.x, q1.y));
        unsigned long long s1 = fadd2(fadd2(q2.x, q2.y), fadd2(q3.x, q3.y));
        unsigned long long s2 = fadd2(fadd2(q4.x, q4.y), fadd2(q5.x, q5.y));
        unsigned long long s3 = fadd2(fadd2(q6.x, q6.y), fadd2(q7.x, q7.y));
        unsigned long long ss = fadd2(fadd2(s0, s1), fadd2(s2, s3));
        float slo, shi;
        unpack2(ss, slo, shi);
        float sig = slo + shi;

        // ---- scale + outputs (log/store off the carried path)
        float r = __frcp_rn(sig);
        float lsig = __logf(sig);
        if (j == 0) outb[t - 1] = S + lsig;
        S += m_cur + lsig;

        u = (er_cur * tmp) * r;          // u_t

        // rotate queues
        er_cur = e_q1;  m_cur = m_q1;
        e_q1 = e_q2;    m_q1 = m_q2;
        e_q2 = e_q3;    m_q2 = m_q3;
        e_q3 = e_new;   m_q3 = m_new;
    }

    // epilogue: out[T-1]
    float sigF = wsum(u);
    if (j == 0) outb[T_ - 1] = S + __logf(sigF);
}

extern "C" void kernel_launch(void* const* d_in, const int* in_sizes, int n_in,
                              void* d_out, int out_size)
{
    const float* X       = (const float*)d_in[0];  // (B,T,D)
    const float* Tm      = (const float*)d_in[1];  // (N,N)
    const float* priors  = (const float*)d_in[2];  // (N,)
    const float* mus     = (const float*)d_in[3];  // (N,D)
    const float* logvars = (const float*)d_in[4];  // (N,D)
    float* outp          = (float*)d_out;          // (B,T)

    float *E, *M;
    cudaGetSymbolAddress((void**)&E, g_E);
    cudaGetSymbolAddress((void**)&M, g_M);

    dim3 egrid(T_ / TILE_T, B_);
    emission_kernel<<<egrid, 256>>>(X, mus, logvars);
    forward_kernel<<<B_, 32>>>(Tm, priors, E, M, outp);
}

// round 12
// speedup vs baseline: 2.2710x; 1.0521x over previous
#include <cuda_runtime.h>
#include <cuda_bf16.h>

#define B_ 64
#define T_ 4096
#define N_ 32
#define D_ 64
#define LOG2PI_F 1.837877066409345f
#define PAD_T 8
#define NSA (T_ / 4)

// Scratch: E = exp(logB - M) (padded for branch-free prefetch), per-t max M,
// unnormalized forward vectors V, and per-4-step applied-scale logs SA.
__device__ float g_E[((size_t)B_ * T_ + PAD_T) * N_];
__device__ float g_M[(size_t)B_ * T_ + PAD_T];
__device__ float g_V[(size_t)B_ * T_ * N_];
__device__ float g_SA[(size_t)B_ * NSA];

__device__ __forceinline__ float wmax(float v) {
    #pragma unroll
    for (int o = 16; o; o >>= 1) v = fmaxf(v, __shfl_xor_sync(0xffffffffu, v, o));
    return v;
}
__device__ __forceinline__ float wsum(float v) {
    #pragma unroll
    for (int o = 16; o; o >>= 1) v += __shfl_xor_sync(0xffffffffu, v, o);
    return v;
}

// ---- packed f32x2 helpers ----
__device__ __forceinline__ unsigned long long ffma2(
    unsigned long long a, unsigned long long b, unsigned long long c) {
    unsigned long long d;
    asm("fma.rn.f32x2 %0, %1, %2, %3;" : "=l"(d) : "l"(a), "l"(b), "l"(c));
    return d;
}
__device__ __forceinline__ unsigned long long fadd2(
    unsigned long long a, unsigned long long b) {
    unsigned long long d;
    asm("add.rn.f32x2 %0, %1, %2;" : "=l"(d) : "l"(a), "l"(b));
    return d;
}
__device__ __forceinline__ unsigned long long pack2(float lo, float hi) {
    unsigned long long d;
    asm("mov.b64 %0, {%1, %2};" : "=l"(d) : "f"(lo), "f"(hi));
    return d;
}
__device__ __forceinline__ void unpack2(unsigned long long v, float& lo, float& hi) {
    asm("mov.b64 {%0, %1}, %2;" : "=f"(lo), "=f"(hi) : "l"(v));
}

// ---------------------------------------------------------------------------
// Kernel 1: emissions (unchanged; passed at 2e-6).
// ---------------------------------------------------------------------------
#define TILE_T 64
#define ROWS_PT 8

__global__ void __launch_bounds__(256) emission_kernel(
    const float* __restrict__ X,
    const float* __restrict__ mus,
    const float* __restrict__ logvars)
{
    __shared__ float4 ivs4[16 * 32];
    __shared__ float4 ws4[16 * 32];
    __shared__ float4 Xs4[TILE_T * 16];
    __shared__ float  Kc[32];

    const int tid = threadIdx.x;
    const int b   = blockIdx.y;
    const int t0  = blockIdx.x * TILE_T;

    float* ivs = reinterpret_cast<float*>(ivs4);
    float* ws  = reinterpret_cast<float*>(ws4);

    for (int idx = tid; idx < N_ * D_; idx += 256) {
        int n = idx >> 6;
        int d = idx & 63;
        float lv = logvars[idx];
        float iv = __expf(-lv);
        int off = ((d >> 2) * 32 + n) * 4 + (d & 3);
        ivs[off] = iv;
        ws[off]  = -2.0f * mus[idx] * iv;
    }
    const float4* Xv = reinterpret_cast<const float4*>(X + ((size_t)b * T_ + t0) * D_);
    for (int idx = tid; idx < TILE_T * 16; idx += 256) Xs4[idx] = Xv[idx];
    __syncthreads();

    if (tid < N_) {
        float k = D_ * LOG2PI_F;
        #pragma unroll 8
        for (int d = 0; d < D_; ++d) {
            float mu = mus[tid * D_ + d];
            float iv = ivs[((d >> 2) * 32 + tid) * 4 + (d & 3)];
            k += mu * mu * iv + logvars[tid * D_ + d];
        }
        Kc[tid] = k;
    }
    __syncthreads();

    const int n    = tid & 31;
    const int slot = tid >> 5;
    const int tb   = slot * ROWS_PT;

    float acc[ROWS_PT];
    #pragma unroll
    for (int r = 0; r < ROWS_PT; ++r) acc[r] = 0.f;

    #pragma unroll
    for (int d4 = 0; d4 < 16; ++d4) {
        float4 iv = ivs4[d4 * 32 + n];
        float4 w  = ws4[d4 * 32 + n];
        #pragma unroll
        for (int r = 0; r < ROWS_PT; ++r) {
            float4 x = Xs4[(tb + r) * 16 + d4];
            float a = acc[r];
            a = fmaf(x.x, fmaf(x.x, iv.x, w.x), a);
            a = fmaf(x.y, fmaf(x.y, iv.y, w.y), a);
            a = fmaf(x.z, fmaf(x.z, iv.z, w.z), a);
            a = fmaf(x.w, fmaf(x.w, iv.w, w.w), a);
            acc[r] = a;
        }
    }
    const float k = Kc[n];
    const size_t tg = (size_t)b * T_ + t0 + tb;
    float* ep = g_E + tg * N_ + n;
    float* mp = g_M + tg;
    #pragma unroll
    for (int r = 0; r < ROWS_PT; ++r) {
        float v = -0.5f * (acc[r] + k);
        float m = wmax(v);
        ep[(size_t)r * N_] = __expf(v - m);
        if (n == 0) mp[r] = m;
    }
}

// ---------------------------------------------------------------------------
// Kernel 2: forward recursion, MINIMAL loop. Only v_t = e_t o (A^T v_{t-1}),
// rescaled every 4 steps by r = rcp(sigma(v_{t-4})) (computed 3 iters earlier
// -> off-path; no per-step feedback). v_t stored to gmem; all log/sum/output
// work deferred to finalize_kernel. Scale logs recorded exactly in SA.
// ---------------------------------------------------------------------------
__global__ void __launch_bounds__(32, 1) forward_kernel(
    const float* __restrict__ Tm,
    const float* __restrict__ priors,
    const float* __restrict__ Eb,
    float* __restrict__ V,
    float* __restrict__ SA)
{
    __shared__ __align__(16) float ubuf[2][N_];

    const int b = blockIdx.x;
    const int j = threadIdx.x;

    // A[i][j] = softmax(row i)[j]; packed column as 16 f32x2 pairs
    float Acol[N_];
    #pragma unroll
    for (int i = 0; i < N_; ++i) {
        float raw = Tm[i * N_ + j];
        float mx  = wmax(raw);
        float e   = __expf(raw - mx);
        float s   = wsum(e);
        Acol[i]   = e * __frcp_rn(s);
    }
    unsigned long long A2[N_ / 2];
    #pragma unroll
    for (int p = 0; p < N_ / 2; ++p) A2[p] = pack2(Acol[2 * p], Acol[2 * p + 1]);

    // pi (linear, normalized once)
    float p  = priors[j];
    float pm = wmax(p);
    float pe = __expf(p - pm);
    float ps = wsum(pe);
    float pi = pe * __frcp_rn(ps);

    const float* Ep = Eb + (size_t)b * T_ * N_ + j;
    float* Vp  = V + (size_t)b * T_ * N_ + j;
    float* SAp = SA + (size_t)b * NSA;

    // v_0 = pi o E_0 ; SA[0] = 0 (no scale applied yet)
    float u = pi * Ep[0];
    Vp[0] = u;
    if (j == 0) SAp[0] = 0.f;
    float S = 0.f;

    // E queue, prefetch distance 8 (padded arrays -> branch-free)
    float er_cur = Ep[(size_t)1 * N_];
    float e_q1 = Ep[(size_t)2 * N_];
    float e_q2 = Ep[(size_t)3 * N_];
    float e_q3 = Ep[(size_t)4 * N_];
    float e_q4 = Ep[(size_t)5 * N_];
    float e_q5 = Ep[(size_t)6 * N_];
    float e_q6 = Ep[(size_t)7 * N_];

    float r_cur = 1.0f, l_cur = 0.0f;   // set at t=4k+1, used at t=4k+4

    #pragma unroll 4
    for (int t = 1; t < T_; ++t) {
        float e_new = Ep[(size_t)(t + 7) * N_];

        // publish v_{t-1}, broadcast-read as 8 x 16B
        const int buf = t & 1;
        ubuf[buf][j] = u;
        __syncwarp();
        const ulonglong2* uv = reinterpret_cast<const ulonglong2*>(ubuf[buf]);
        ulonglong2 q0 = uv[0], q1 = uv[1], q2 = uv[2], q3 = uv[3];
        ulonglong2 q4 = uv[4], q5 = uv[5], q6 = uv[6], q7 = uv[7];

        // matvec (packed): tmp[j] = sum_i v_{t-1}[i] * A[i][j]
        unsigned long long c0, c1, c2, c3;
        c0 = ffma2(q0.x, A2[0], ffma2(q0.y, A2[1], 0ull));
        c1 = ffma2(q1.x, A2[2], ffma2(q1.y, A2[3], 0ull));
        c2 = ffma2(q2.x, A2[4], ffma2(q2.y, A2[5], 0ull));
        c3 = ffma2(q3.x, A2[6], ffma2(q3.y, A2[7], 0ull));
        c0 = ffma2(q4.x, A2[8],  ffma2(q4.y, A2[9],  c0));
        c1 = ffma2(q5.x, A2[10], ffma2(q5.y, A2[11], c1));
        c2 = ffma2(q6.x, A2[12], ffma2(q6.y, A2[13], c2));
        c3 = ffma2(q7.x, A2[14], ffma2(q7.y, A2[15], c3));
        unsigned long long cs = fadd2(fadd2(c0, c1), fadd2(c2, c3));
        float clo, chi;
        unpack2(cs, clo, chi);
        float un = er_cur * (clo + chi);

        if ((t & 3) == 1) {
            // sigma(v_{t-1}) where t-1 = 4k: packed tree over the broadcasts.
            // Result (rcp + log) consumed 3 iterations later -> off-path.
            unsigned long long s0 = fadd2(fadd2(q0.x, q0.y), fadd2(q1.x, q1.y));
            unsigned long long s1 = fadd2(fadd2(q2.x, q2.y), fadd2(q3.x, q3.y));
            unsigned long long s2 = fadd2(fadd2(q4.x, q4.y), fadd2(q5.x, q5.y));
            unsigned long long s3 = fadd2(fadd2(q6.x, q6.y), fadd2(q7.x, q7.y));
            unsigned long long ss = fadd2(fadd2(s0, s1), fadd2(s2, s3));
            float slo, shi;
            unpack2(ss, slo, shi);
            float sig = slo + shi;
            r_cur = __frcp_rn(sig);
            l_cur = __logf(sig);
        }
        if ((t & 3) == 0) {
            // apply (and exactly log) the pending rescale
            un *= r_cur;
            S += l_cur;
            if (j == 0) SAp[t >> 2] = S;
        }

        Vp[(size_t)t * N_] = un;   // off-path store
        u = un;

        // rotate E queue
        er_cur = e_q1; e_q1 = e_q2; e_q2 = e_q3; e_q3 = e_q4;
        e_q4 = e_q5;   e_q5 = e_q6; e_q6 = e_new;
    }
}

// ---------------------------------------------------------------------------
// Kernel 3: finalize. out[b,t] = prefixM[b,t] + SA[b,t/4] + log(sum_n v_t[n]).
// One block of 1024 threads per batch; each thread owns t = 4*tid..4*tid+3
// (so SA index == tid). Block-level inclusive scan of M via warp shfl scans.
// ---------------------------------------------------------------------------
__global__ void __launch_bounds__(1024) finalize_kernel(
    const float* __restrict__ V,
    const float* __restrict__ M,
    const float* __restrict__ SA,
    float* __restrict__ out)
{
    __shared__ float wsums[32];
    const unsigned FULL = 0xffffffffu;
    const int b    = blockIdx.x;
    const int tid  = threadIdx.x;
    const int lane = tid & 31;
    const int wid  = tid >> 5;

    // local inclusive prefix of this thread's 4 M values
    float4 m4 = reinterpret_cast<const float4*>(M + (size_t)b * T_)[tid];
    float s0 = m4.x;
    float s1 = s0 + m4.y;
    float s2 = s1 + m4.z;
    float s3 = s2 + m4.w;

    // warp inclusive scan of per-thread totals
    float sc = s3;
    #pragma unroll
    for (int o = 1; o < 32; o <<= 1) {
        float v = __shfl_up_sync(FULL, sc, o);
        if (lane >= o) sc += v;
    }
    if (lane == 31) wsums[wid] = sc;
    __syncthreads();
    if (wid == 0) {
        float w = wsums[lane];
        #pragma unroll
        for (int o = 1; o < 32; o <<= 1) {
            float v = __shfl_up_sync(FULL, w, o);
            if (lane >= o) w += v;
        }
        wsums[lane] = w;
    }
    __syncthreads();
    float base = (wid > 0 ? wsums[wid - 1] : 0.f) + (sc - s3);  // exclusive prefix

    const float sa = SA[(size_t)b * NSA + tid];
    const float4* Vb = reinterpret_cast<const float4*>(
        V + ((size_t)b * T_ + 4 * (size_t)tid) * N_);
    float* outp = out + (size_t)b * T_ + 4 * tid;

    float pmv[4] = {base + s0, base + s1, base + s2, base + s3};
    #pragma unroll
    for (int r = 0; r < 4; ++r) {
        float4 a0 = Vb[r * 8 + 0], a1 = Vb[r * 8 + 1];
        float4 a2 = Vb[r * 8 + 2], a3 = Vb[r * 8 + 3];
        float4 a4 = Vb[r * 8 + 4], a5 = Vb[r * 8 + 5];
        float4 a6 = Vb[r * 8 + 6], a7 = Vb[r * 8 + 7];
        float t0 = ((a0.x + a0.y) + (a0.z + a0.w)) + ((a1.x + a1.y) + (a1.z + a1.w));
        float t1 = ((a2.x + a2.y) + (a2.z + a2.w)) + ((a3.x + a3.y) + (a3.z + a3.w));
        float t2 = ((a4.x + a4.y) + (a4.z + a4.w)) + ((a5.x + a5.y) + (a5.z + a5.w));
        float t3 = ((a6.x + a6.y) + (a6.z + a6.w)) + ((a7.x + a7.y) + (a7.z + a7.w));
        float sum = (t0 + t1) + (t2 + t3);
        outp[r] = pmv[r] + sa + __logf(sum);
    }
}

extern "C" void kernel_launch(void* const* d_in, const int* in_sizes, int n_in,
                              void* d_out, int out_size)
{
    const float* X       = (const float*)d_in[0];  // (B,T,D)
    const float* Tm      = (const float*)d_in[1];  // (N,N)
    const float* priors  = (const float*)d_in[2];  // (N,)
    const float* mus     = (const float*)d_in[3];  // (N,D)
    const float* logvars = (const float*)d_in[4];  // (N,D)
    float* outp          = (float*)d_out;          // (B,T)

    float *E, *M, *V, *SA;
    cudaGetSymbolAddress((void**)&E, g_E);
    cudaGetSymbolAddress((void**)&M, g_M);
    cudaGetSymbolAddress((void**)&V, g_V);
    cudaGetSymbolAddress((void**)&SA, g_SA);

    dim3 egrid(T_ / TILE_T, B_);
    emission_kernel<<<egrid, 256>>>(X, mus, logvars);
    forward_kernel<<<B_, 32>>>(Tm, priors, E, V, SA);
    finalize_kernel<<<B_, 1024>>>(V, M, SA, outp);
}

// round 14
// speedup vs baseline: 2.2743x; 1.0015x over previous
#include <cuda_runtime.h>
#include <cuda_bf16.h>

#define B_ 64
#define T_ 4096
#define N_ 32
#define D_ 64
#define LOG2PI_F 1.837877066409345f
#define PAD_T 8
#define NSA (T_ / 4)

// Scratch: E = exp(logB - M) (padded for branch-free prefetch), per-t max M,
// unnormalized forward vectors V, and per-4-step applied-scale logs SA.
__device__ float g_E[((size_t)B_ * T_ + PAD_T) * N_];
__device__ float g_M[(size_t)B_ * T_ + PAD_T];
__device__ float g_V[(size_t)B_ * T_ * N_];
__device__ float g_SA[(size_t)B_ * NSA];

__device__ __forceinline__ float wmax(float v) {
    #pragma unroll
    for (int o = 16; o; o >>= 1) v = fmaxf(v, __shfl_xor_sync(0xffffffffu, v, o));
    return v;
}
__device__ __forceinline__ float wsum(float v) {
    #pragma unroll
    for (int o = 16; o; o >>= 1) v += __shfl_xor_sync(0xffffffffu, v, o);
    return v;
}

// ---- packed f32x2 helpers ----
__device__ __forceinline__ unsigned long long ffma2(
    unsigned long long a, unsigned long long b, unsigned long long c) {
    unsigned long long d;
    asm("fma.rn.f32x2 %0, %1, %2, %3;" : "=l"(d) : "l"(a), "l"(b), "l"(c));
    return d;
}
__device__ __forceinline__ unsigned long long fadd2(
    unsigned long long a, unsigned long long b) {
    unsigned long long d;
    asm("add.rn.f32x2 %0, %1, %2;" : "=l"(d) : "l"(a), "l"(b));
    return d;
}
__device__ __forceinline__ unsigned long long pack2(float lo, float hi) {
    unsigned long long d;
    asm("mov.b64 %0, {%1, %2};" : "=l"(d) : "f"(lo), "f"(hi));
    return d;
}
__device__ __forceinline__ void unpack2(unsigned long long v, float& lo, float& hi) {
    asm("mov.b64 {%0, %1}, %2;" : "=f"(lo), "=f"(hi) : "l"(v));
}

// ---------------------------------------------------------------------------
// Kernel 1: emissions. TILE_T=64 (known-good R12 config, 33KB smem OK).
// ---------------------------------------------------------------------------
#define TILE_T 64
#define ROWS_PT 8

__global__ void __launch_bounds__(256) emission_kernel(
    const float* __restrict__ X,
    const float* __restrict__ mus,
    const float* __restrict__ logvars)
{
    __shared__ float4 ivs4[16 * 32];
    __shared__ float4 ws4[16 * 32];
    __shared__ float4 Xs4[TILE_T * 16];
    __shared__ float  Kc[32];

    const int tid = threadIdx.x;
    const int b   = blockIdx.y;
    const int t0  = blockIdx.x * TILE_T;

    float* ivs = reinterpret_cast<float*>(ivs4);
    float* ws  = reinterpret_cast<float*>(ws4);

    for (int idx = tid; idx < N_ * D_; idx += 256) {
        int n = idx >> 6;
        int d = idx & 63;
        float lv = logvars[idx];
        float iv = __expf(-lv);
        int off = ((d >> 2) * 32 + n) * 4 + (d & 3);
        ivs[off] = iv;
        ws[off]  = -2.0f * mus[idx] * iv;
    }
    const float4* Xv = reinterpret_cast<const float4*>(X + ((size_t)b * T_ + t0) * D_);
    for (int idx = tid; idx < TILE_T * 16; idx += 256) Xs4[idx] = Xv[idx];
    __syncthreads();

    if (tid < N_) {
        float k = D_ * LOG2PI_F;
        #pragma unroll 8
        for (int d = 0; d < D_; ++d) {
            float mu = mus[tid * D_ + d];
            float iv = ivs[((d >> 2) * 32 + tid) * 4 + (d & 3)];
            k += mu * mu * iv + logvars[tid * D_ + d];
        }
        Kc[tid] = k;
    }
    __syncthreads();

    const int n    = tid & 31;
    const int slot = tid >> 5;
    const int tb   = slot * ROWS_PT;

    float acc[ROWS_PT];
    #pragma unroll
    for (int r = 0; r < ROWS_PT; ++r) acc[r] = 0.f;

    #pragma unroll
    for (int d4 = 0; d4 < 16; ++d4) {
        float4 iv = ivs4[d4 * 32 + n];
        float4 w  = ws4[d4 * 32 + n];
        #pragma unroll
        for (int r = 0; r < ROWS_PT; ++r) {
            float4 x = Xs4[(tb + r) * 16 + d4];
            float a = acc[r];
            a = fmaf(x.x, fmaf(x.x, iv.x, w.x), a);
            a = fmaf(x.y, fmaf(x.y, iv.y, w.y), a);
            a = fmaf(x.z, fmaf(x.z, iv.z, w.z), a);
            a = fmaf(x.w, fmaf(x.w, iv.w, w.w), a);
            acc[r] = a;
        }
    }
    const float k = Kc[n];
    const size_t tg = (size_t)b * T_ + t0 + tb;
    float* ep = g_E + tg * N_ + n;
    float* mp = g_M + tg;
    #pragma unroll
    for (int r = 0; r < ROWS_PT; ++r) {
        float v = -0.5f * (acc[r] + k);
        float m = wmax(v);
        ep[(size_t)r * N_] = __expf(v - m);
        if (n == 0) mp[r] = m;
    }
}

// ---------------------------------------------------------------------------
// Kernel 2: forward recursion, minimal loop. One warp per block -> __syncthreads
// compiles to BAR.SYNC (3cy floor at nw=1, natively drains STS) instead of
// WARPSYNC (~23cy). Loop computes only v_t = e_t o (A^T v_{t-1}) with a
// rescale every 4 steps (sigma computed 3 iters earlier -> off-path, logged
// exactly into SA). All sums/logs/outputs deferred to finalize_kernel.
// ---------------------------------------------------------------------------
__global__ void __launch_bounds__(32, 1) forward_kernel(
    const float* __restrict__ Tm,
    const float* __restrict__ priors,
    const float* __restrict__ Eb,
    float* __restrict__ V,
    float* __restrict__ SA)
{
    __shared__ __align__(16) float ubuf[2][N_];

    const int b = blockIdx.x;
    const int j = threadIdx.x;

    // A[i][j] = softmax(row i)[j]; packed column as 16 f32x2 pairs
    float Acol[N_];
    #pragma unroll
    for (int i = 0; i < N_; ++i) {
        float raw = Tm[i * N_ + j];
        float mx  = wmax(raw);
        float e   = __expf(raw - mx);
        float s   = wsum(e);
        Acol[i]   = e * __frcp_rn(s);
    }
    unsigned long long A2[N_ / 2];
    #pragma unroll
    for (int p = 0; p < N_ / 2; ++p) A2[p] = pack2(Acol[2 * p], Acol[2 * p + 1]);

    // pi (linear, normalized once)
    float p  = priors[j];
    float pm = wmax(p);
    float pe = __expf(p - pm);
    float ps = wsum(pe);
    float pi = pe * __frcp_rn(ps);

    const float* Ep = Eb + (size_t)b * T_ * N_ + j;
    float* Vp  = V + (size_t)b * T_ * N_ + j;
    float* SAp = SA + (size_t)b * NSA;

    // v_0 = pi o E_0 ; SA[0] = 0
    float u = pi * Ep[0];
    Vp[0] = u;
    if (j == 0) SAp[0] = 0.f;
    float S = 0.f;

    // E queue, prefetch distance 8 (padded arrays -> branch-free)
    float er_cur = Ep[(size_t)1 * N_];
    float e_q1 = Ep[(size_t)2 * N_];
    float e_q2 = Ep[(size_t)3 * N_];
    float e_q3 = Ep[(size_t)4 * N_];
    float e_q4 = Ep[(size_t)5 * N_];
    float e_q5 = Ep[(size_t)6 * N_];
    float e_q6 = Ep[(size_t)7 * N_];

    float r_cur = 1.0f, l_cur = 0.0f;   // set at t=4k+1, used at t=4k+4

    #pragma unroll 4
    for (int t = 1; t < T_; ++t) {
        float e_new = Ep[(size_t)(t + 7) * N_];

        // publish v_{t-1}, broadcast-read as 8 x 16B.
        // One-warp block: __syncthreads == BAR.SYNC, 3cy floor + STS drain.
        const int buf = t & 1;
        ubuf[buf][j] = u;
        __syncthreads();
        const ulonglong2* uv = reinterpret_cast<const ulonglong2*>(ubuf[buf]);
        ulonglong2 q0 = uv[0], q1 = uv[1], q2 = uv[2], q3 = uv[3];
        ulonglong2 q4 = uv[4], q5 = uv[5], q6 = uv[6], q7 = uv[7];

        // matvec (packed): tmp[j] = sum_i v_{t-1}[i] * A[i][j]
        unsigned long long c0, c1, c2, c3;
        c0 = ffma2(q0.x, A2[0], ffma2(q0.y, A2[1], 0ull));
        c1 = ffma2(q1.x, A2[2], ffma2(q1.y, A2[3], 0ull));
        c2 = ffma2(q2.x, A2[4], ffma2(q2.y, A2[5], 0ull));
        c3 = ffma2(q3.x, A2[6], ffma2(q3.y, A2[7], 0ull));
        c0 = ffma2(q4.x, A2[8],  ffma2(q4.y, A2[9],  c0));
        c1 = ffma2(q5.x, A2[10], ffma2(q5.y, A2[11], c1));
        c2 = ffma2(q6.x, A2[12], ffma2(q6.y, A2[13], c2));
        c3 = ffma2(q7.x, A2[14], ffma2(q7.y, A2[15], c3));
        unsigned long long cs = fadd2(fadd2(c0, c1), fadd2(c2, c3));
        float clo, chi;
        unpack2(cs, clo, chi);
        float un = er_cur * (clo + chi);

        if ((t & 3) == 1) {
            // sigma(v_{t-1}) where t-1 = 4k (post-rescale value):
            // consumed 3 iterations later -> off the carried path.
            unsigned long long s0 = fadd2(fadd2(q0.x, q0.y), fadd2(q1.x, q1.y));
            unsigned long long s1 = fadd2(fadd2(q2.x, q2.y), fadd2(q3.x, q3.y));
            unsigned long long s2 = fadd2(fadd2(q4.x, q4.y), fadd2(q5.x, q5.y));
            unsigned long long s3 = fadd2(fadd2(q6.x, q6.y), fadd2(q7.x, q7.y));
            unsigned long long ss = fadd2(fadd2(s0, s1), fadd2(s2, s3));
            float slo, shi;
            unpack2(ss, slo, shi);
            float sig = slo + shi;
            r_cur = __frcp_rn(sig);
            l_cur = __logf(sig);
        }
        if ((t & 3) == 0) {
            un *= r_cur;
            S += l_cur;
            if (j == 0) SAp[t >> 2] = S;
        }

        Vp[(size_t)t * N_] = un;   // off-path store
        u = un;

        // rotate E queue
        er_cur = e_q1; e_q1 = e_q2; e_q2 = e_q3; e_q3 = e_q4;
        e_q4 = e_q5;   e_q5 = e_q6; e_q6 = e_new;
    }
}

// ---------------------------------------------------------------------------
// Kernel 3: finalize. out[b,t] = prefixM[b,t] + SA[b,t/4] + log(sum_n v_t[n]).
// ---------------------------------------------------------------------------
__global__ void __launch_bounds__(1024) finalize_kernel(
    const float* __restrict__ V,
    const float* __restrict__ M,
    const float* __restrict__ SA,
    float* __restrict__ out)
{
    __shared__ float wsums[32];
    const unsigned FULL = 0xffffffffu;
    const int b    = blockIdx.x;
    const int tid  = threadIdx.x;
    const int lane = tid & 31;
    const int wid  = tid >> 5;

    float4 m4 = reinterpret_cast<const float4*>(M + (size_t)b * T_)[tid];
    float s0 = m4.x;
    float s1 = s0 + m4.y;
    float s2 = s1 + m4.z;
    float s3 = s2 + m4.w;

    float sc = s3;
    #pragma unroll
    for (int o = 1; o < 32; o <<= 1) {
        float v = __shfl_up_sync(FULL, sc, o);
        if (lane >= o) sc += v;
    }
    if (lane == 31) wsums[wid] = sc;
    __syncthreads();
    if (wid == 0) {
        float w = wsums[lane];
        #pragma unroll
        for (int o = 1; o < 32; o <<= 1) {
            float v = __shfl_up_sync(FULL, w, o);
            if (lane >= o) w += v;
        }
        wsums[lane] = w;
    }
    __syncthreads();
    float base = (wid > 0 ? wsums[wid - 1] : 0.f) + (sc - s3);

    const float sa = SA[(size_t)b * NSA + tid];
    const float4* Vb = reinterpret_cast<const float4*>(
        V + ((size_t)b * T_ + 4 * (size_t)tid) * N_);
    float* outp = out + (size_t)b * T_ + 4 * tid;

    float pmv[4] = {base + s0, base + s1, base + s2, base + s3};
    #pragma unroll
    for (int r = 0; r < 4; ++r) {
        float4 a0 = Vb[r * 8 + 0], a1 = Vb[r * 8 + 1];
        float4 a2 = Vb[r * 8 + 2], a3 = Vb[r * 8 + 3];
        float4 a4 = Vb[r * 8 + 4], a5 = Vb[r * 8 + 5];
        float4 a6 = Vb[r * 8 + 6], a7 = Vb[r * 8 + 7];
        float t0 = ((a0.x + a0.y) + (a0.z + a0.w)) + ((a1.x + a1.y) + (a1.z + a1.w));
        float t1 = ((a2.x + a2.y) + (a2.z + a2.w)) + ((a3.x + a3.y) + (a3.z + a3.w));
        float t2 = ((a4.x + a4.y) + (a4.z + a4.w)) + ((a5.x + a5.y) + (a5.z + a5.w));
        float t3 = ((a6.x + a6.y) + (a6.z + a6.w)) + ((a7.x + a7.y) + (a7.z + a7.w));
        float sum = (t0 + t1) + (t2 + t3);
        outp[r] = pmv[r] + sa + __logf(sum);
    }
}

extern "C" void kernel_launch(void* const* d_in, const int* in_sizes, int n_in,
                              void* d_out, int out_size)
{
    const float* X       = (const float*)d_in[0];  // (B,T,D)
    const float* Tm      = (const float*)d_in[1];  // (N,N)
    const float* priors  = (const float*)d_in[2];  // (N,)
    const float* mus     = (const float*)d_in[3];  // (N,D)
    const float* logvars = (const float*)d_in[4];  // (N,D)
    float* outp          = (float*)d_out;          // (B,T)

    float *E, *M, *V, *SA;
    cudaGetSymbolAddress((void**)&E, g_E);
    cudaGetSymbolAddress((void**)&M, g_M);
    cudaGetSymbolAddress((void**)&V, g_V);
    cudaGetSymbolAddress((void**)&SA, g_SA);

    dim3 egrid(T_ / TILE_T, B_);
    emission_kernel<<<egrid, 256>>>(X, mus, logvars);
    forward_kernel<<<B_, 32>>>(Tm, priors, E, V, SA);
    finalize_kernel<<<B_, 1024>>>(V, M, SA, outp);
}

// round 15
// speedup vs baseline: 6.9187x; 3.0422x over previous
#include <cuda_runtime.h>
#include <cuda_bf16.h>

#define B_ 64
#define T_ 4096
#define N_ 32
#define D_ 64
#define LOG2PI_F 1.837877066409345f
#define PAD_T 8
#define NSA (T_ / 4)
#define CHK 64            // number of chunks per batch
#define CL  64            // chunk (territory) length; CHK*CL == T_
#define HWU 16            // warm-up steps (mixing: eta^15 ~ 1e-7)
#define WPB 4             // chunk-warps per block

// Scratch
__device__ float g_E[((size_t)B_ * T_ + PAD_T) * N_];
__device__ float g_M[(size_t)B_ * T_ + PAD_T];
__device__ float g_V[(size_t)B_ * T_ * N_];
__device__ float g_SA[(size_t)B_ * NSA];
__device__ float g_Wb[(size_t)B_ * CHK];   // warm-up-end logsum per chunk
__device__ float g_Zb[(size_t)B_ * CHK];   // territory-end logsum per chunk
__device__ float g_OFF[(size_t)B_ * CHK];  // spliced per-chunk offsets

__device__ __forceinline__ float wmax(float v) {
    #pragma unroll
    for (int o = 16; o; o >>= 1) v = fmaxf(v, __shfl_xor_sync(0xffffffffu, v, o));
    return v;
}
__device__ __forceinline__ float wsum(float v) {
    #pragma unroll
    for (int o = 16; o; o >>= 1) v += __shfl_xor_sync(0xffffffffu, v, o);
    return v;
}

// ---- packed f32x2 helpers ----
__device__ __forceinline__ unsigned long long ffma2(
    unsigned long long a, unsigned long long b, unsigned long long c) {
    unsigned long long d;
    asm("fma.rn.f32x2 %0, %1, %2, %3;" : "=l"(d) : "l"(a), "l"(b), "l"(c));
    return d;
}
__device__ __forceinline__ unsigned long long fadd2(
    unsigned long long a, unsigned long long b) {
    unsigned long long d;
    asm("add.rn.f32x2 %0, %1, %2;" : "=l"(d) : "l"(a), "l"(b));
    return d;
}
__device__ __forceinline__ unsigned long long pack2(float lo, float hi) {
    unsigned long long d;
    asm("mov.b64 %0, {%1, %2};" : "=l"(d) : "f"(lo), "f"(hi));
    return d;
}
__device__ __forceinline__ void unpack2(unsigned long long v, float& lo, float& hi) {
    asm("mov.b64 {%0, %1}, %2;" : "=f"(lo), "=f"(hi) : "l"(v));
}

// ---------------------------------------------------------------------------
// Kernel 1: emissions (known-good R12 config).
// ---------------------------------------------------------------------------
#define TILE_T 64
#define ROWS_PT 8

__global__ void __launch_bounds__(256) emission_kernel(
    const float* __restrict__ X,
    const float* __restrict__ mus,
    const float* __restrict__ logvars)
{
    __shared__ float4 ivs4[16 * 32];
    __shared__ float4 ws4[16 * 32];
    __shared__ float4 Xs4[TILE_T * 16];
    __shared__ float  Kc[32];

    const int tid = threadIdx.x;
    const int b   = blockIdx.y;
    const int t0  = blockIdx.x * TILE_T;

    float* ivs = reinterpret_cast<float*>(ivs4);
    float* ws  = reinterpret_cast<float*>(ws4);

    for (int idx = tid; idx < N_ * D_; idx += 256) {
        int n = idx >> 6;
        int d = idx & 63;
        float lv = logvars[idx];
        float iv = __expf(-lv);
        int off = ((d >> 2) * 32 + n) * 4 + (d & 3);
        ivs[off] = iv;
        ws[off]  = -2.0f * mus[idx] * iv;
    }
    const float4* Xv = reinterpret_cast<const float4*>(X + ((size_t)b * T_ + t0) * D_);
    for (int idx = tid; idx < TILE_T * 16; idx += 256) Xs4[idx] = Xv[idx];
    __syncthreads();

    if (tid < N_) {
        float k = D_ * LOG2PI_F;
        #pragma unroll 8
        for (int d = 0; d < D_; ++d) {
            float mu = mus[tid * D_ + d];
            float iv = ivs[((d >> 2) * 32 + tid) * 4 + (d & 3)];
            k += mu * mu * iv + logvars[tid * D_ + d];
        }
        Kc[tid] = k;
    }
    __syncthreads();

    const int n    = tid & 31;
    const int slot = tid >> 5;
    const int tb   = slot * ROWS_PT;

    float acc[ROWS_PT];
    #pragma unroll
    for (int r = 0; r < ROWS_PT; ++r) acc[r] = 0.f;

    #pragma unroll
    for (int d4 = 0; d4 < 16; ++d4) {
        float4 iv = ivs4[d4 * 32 + n];
        float4 w  = ws4[d4 * 32 + n];
        #pragma unroll
        for (int r = 0; r < ROWS_PT; ++r) {
            float4 x = Xs4[(tb + r) * 16 + d4];
            float a = acc[r];
            a = fmaf(x.x, fmaf(x.x, iv.x, w.x), a);
            a = fmaf(x.y, fmaf(x.y, iv.y, w.y), a);
            a = fmaf(x.z, fmaf(x.z, iv.z, w.z), a);
            a = fmaf(x.w, fmaf(x.w, iv.w, w.w), a);
            acc[r] = a;
        }
    }
    const float k = Kc[n];
    const size_t tg = (size_t)b * T_ + t0 + tb;
    float* ep = g_E + tg * N_ + n;
    float* mp = g_M + tg;
    #pragma unroll
    for (int r = 0; r < ROWS_PT; ++r) {
        float v = -0.5f * (acc[r] + k);
        float m = wmax(v);
        ep[(size_t)r * N_] = __expf(v - m);
        if (n == 0) mp[r] = m;
    }
}

// ---------------------------------------------------------------------------
// Kernel 2: CHUNKED forward. Each warp owns chunk c of batch b: territory
// t in [c*CL, (c+1)*CL). Chunks c>=1 start HWU steps early from E[t_init]
// (arbitrary positive start); Birkhoff contraction mixes the direction to
// ~1e-7 before territory entry. Outputs exact up to one scalar/chunk, fixed
// by boundary splice: both chunk c-1 (Z) and chunk c (W) evaluate t=c*CL-1.
// Rescale every 4 global steps (sigma measured 3 iters earlier), logged
// exactly into chunk-local SA.
// ---------------------------------------------------------------------------
__global__ void __launch_bounds__(32 * WPB) forward_chunk_kernel(
    const float* __restrict__ Tm,
    const float* __restrict__ priors,
    const float* __restrict__ Eb,
    float* __restrict__ V,
    float* __restrict__ SA,
    float* __restrict__ Wb,
    float* __restrict__ Zb)
{
    __shared__ __align__(16) float ubuf[WPB][2][N_];

    const int b  = blockIdx.x;
    const int w  = threadIdx.x >> 5;
    const int c  = blockIdx.y * WPB + w;
    const int j  = threadIdx.x & 31;

    // A column j (softmax rows), packed into f32x2 pairs
    float Acol[N_];
    #pragma unroll
    for (int i = 0; i < N_; ++i) {
        float raw = Tm[i * N_ + j];
        float mx  = wmax(raw);
        float e   = __expf(raw - mx);
        float s   = wsum(e);
        Acol[i]   = e * __frcp_rn(s);
    }
    unsigned long long A2[N_ / 2];
    #pragma unroll
    for (int p = 0; p < N_ / 2; ++p) A2[p] = pack2(Acol[2 * p], Acol[2 * p + 1]);

    // pi (used by chunk 0 only)
    float p  = priors[j];
    float pm = wmax(p);
    float pe = __expf(p - pm);
    float ps = wsum(pe);
    float pi = pe * __frcp_rn(ps);

    const float* Ep = Eb + (size_t)b * T_ * N_ + j;
    float* Vp  = V + (size_t)b * T_ * N_ + j;
    float* SAp = SA + (size_t)b * NSA;

    const int terr   = c * CL;
    const int tinit  = (c == 0) ? 0 : terr - HWU;
    const int tend   = terr + CL;

    // init
    float u;
    if (c == 0) {
        u = pi * Ep[0];
        Vp[0] = u;
        if (j == 0) SAp[0] = 0.f;
    } else {
        u = Ep[(size_t)tinit * N_];      // arbitrary positive start
    }
    float S = 0.f;
    float r_cur = 1.0f, l_cur = 0.0f;

    // E queue, prefetch distance 4 (E padded by PAD_T -> branch-free)
    float er_cur = Ep[(size_t)(tinit + 1) * N_];
    float e_q1   = Ep[(size_t)(tinit + 2) * N_];
    float e_q2   = Ep[(size_t)(tinit + 3) * N_];
    float e_q3   = Ep[(size_t)(tinit + 4) * N_];

    for (int t = tinit + 1; t < tend; ++t) {
        float e_new = Ep[(size_t)(t + 4) * N_];

        // publish v_{t-1}, broadcast-read as 8 x 16B (per-warp buffer)
        const int buf = t & 1;
        ubuf[w][buf][j] = u;
        __syncwarp();
        const ulonglong2* uv = reinterpret_cast<const ulonglong2*>(ubuf[w][buf]);
        ulonglong2 q0 = uv[0], q1 = uv[1], q2 = uv[2], q3 = uv[3];
        ulonglong2 q4 = uv[4], q5 = uv[5], q6 = uv[6], q7 = uv[7];

        // matvec (packed): tmp[j] = sum_i v_{t-1}[i] * A[i][j]
        unsigned long long c0, c1, c2, c3;
        c0 = ffma2(q0.x, A2[0], ffma2(q0.y, A2[1], 0ull));
        c1 = ffma2(q1.x, A2[2], ffma2(q1.y, A2[3], 0ull));
        c2 = ffma2(q2.x, A2[4], ffma2(q2.y, A2[5], 0ull));
        c3 = ffma2(q3.x, A2[6], ffma2(q3.y, A2[7], 0ull));
        c0 = ffma2(q4.x, A2[8],  ffma2(q4.y, A2[9],  c0));
        c1 = ffma2(q5.x, A2[10], ffma2(q5.y, A2[11], c1));
        c2 = ffma2(q6.x, A2[12], ffma2(q6.y, A2[13], c2));
        c3 = ffma2(q7.x, A2[14], ffma2(q7.y, A2[15], c3));
        unsigned long long cs = fadd2(fadd2(c0, c1), fadd2(c2, c3));
        float clo, chi;
        unpack2(cs, clo, chi);
        float un = er_cur * (clo + chi);

        if ((t & 3) == 1) {
            // sigma(v_{t-1}) (post-rescale vector), consumed 3 iters later
            unsigned long long s0 = fadd2(fadd2(q0.x, q0.y), fadd2(q1.x, q1.y));
            unsigned long long s1 = fadd2(fadd2(q2.x, q2.y), fadd2(q3.x, q3.y));
            unsigned long long s2 = fadd2(fadd2(q4.x, q4.y), fadd2(q5.x, q5.y));
            unsigned long long s3 = fadd2(fadd2(q6.x, q6.y), fadd2(q7.x, q7.y));
            unsigned long long ss = fadd2(fadd2(s0, s1), fadd2(s2, s3));
            float slo, shi;
            unpack2(ss, slo, shi);
            float sig = slo + shi;
            r_cur = __frcp_rn(sig);
            l_cur = __logf(sig);
        }
        if ((t & 3) == 0) {
            un *= r_cur;
            S += l_cur;
            if (j == 0 && t >= terr) SAp[t >> 2] = S;
        }

        if (t >= terr) Vp[(size_t)t * N_] = un;

        if (t == terr - 1) {                 // warm-up end (chunks c>=1 only)
            float sg = wsum(un);
            if (j == 0) Wb[b * CHK + c] = S + __logf(sg);
        }
        if (t == tend - 1) {                 // territory end
            float sg = wsum(un);
            if (j == 0) Zb[b * CHK + c] = S + __logf(sg);
        }

        u = un;
        er_cur = e_q1; e_q1 = e_q2; e_q2 = e_q3; e_q3 = e_new;
    }
}

// ---------------------------------------------------------------------------
// Kernel 2b: splice. OFF[b,0]=0; OFF[b,c] = OFF[b,c-1] + Z[b,c-1] - W[b,c].
// ---------------------------------------------------------------------------
__global__ void splice_kernel(
    const float* __restrict__ Wb,
    const float* __restrict__ Zb,
    float* __restrict__ OFF)
{
    const int b = blockIdx.x;
    if (threadIdx.x == 0) {
        float off = 0.f;
        OFF[b * CHK] = 0.f;
        for (int c = 1; c < CHK; ++c) {
            off += Zb[b * CHK + c - 1] - Wb[b * CHK + c];
            OFF[b * CHK + c] = off;
        }
    }
}

// ---------------------------------------------------------------------------
// Kernel 3: finalize.
// out[b,t] = prefixM[b,t] + SA[b,t/4] + OFF[b,t/CL] + log(sum_n V_t[n]).
// ---------------------------------------------------------------------------
__global__ void __launch_bounds__(1024) finalize_kernel(
    const float* __restrict__ V,
    const float* __restrict__ M,
    const float* __restrict__ SA,
    const float* __restrict__ OFF,
    float* __restrict__ out)
{
    __shared__ float wsums[32];
    const unsigned FULL = 0xffffffffu;
    const int b    = blockIdx.x;
    const int tid  = threadIdx.x;
    const int lane = tid & 31;
    const int wid  = tid >> 5;

    float4 m4 = reinterpret_cast<const float4*>(M + (size_t)b * T_)[tid];
    float s0 = m4.x;
    float s1 = s0 + m4.y;
    float s2 = s1 + m4.z;
    float s3 = s2 + m4.w;

    float sc = s3;
    #pragma unroll
    for (int o = 1; o < 32; o <<= 1) {
        float v = __shfl_up_sync(FULL, sc, o);
        if (lane >= o) sc += v;
    }
    if (lane == 31) wsums[wid] = sc;
    __syncthreads();
    if (wid == 0) {
        float w = wsums[lane];
        #pragma unroll
        for (int o = 1; o < 32; o <<= 1) {
            float v = __shfl_up_sync(FULL, w, o);
            if (lane >= o) w += v;
        }
        wsums[lane] = w;
    }
    __syncthreads();
    float base = (wid > 0 ? wsums[wid - 1] : 0.f) + (sc - s3);

    const float sa  = SA[(size_t)b * NSA + tid];
    const float ofc = OFF[(size_t)b * CHK + tid / (CL / 4)];
    const float4* Vb = reinterpret_cast<const float4*>(
        V + ((size_t)b * T_ + 4 * (size_t)tid) * N_);
    float* outp = out + (size_t)b * T_ + 4 * tid;

    float pmv[4] = {base + s0, base + s1, base + s2, base + s3};
    #pragma unroll
    for (int r = 0; r < 4; ++r) {
        float4 a0 = Vb[r * 8 + 0], a1 = Vb[r * 8 + 1];
        float4 a2 = Vb[r * 8 + 2], a3 = Vb[r * 8 + 3];
        float4 a4 = Vb[r * 8 + 4], a5 = Vb[r * 8 + 5];
        float4 a6 = Vb[r * 8 + 6], a7 = Vb[r * 8 + 7];
        float t0 = ((a0.x + a0.y) + (a0.z + a0.w)) + ((a1.x + a1.y) + (a1.z + a1.w));
        float t1 = ((a2.x + a2.y) + (a2.z + a2.w)) + ((a3.x + a3.y) + (a3.z + a3.w));
        float t2 = ((a4.x + a4.y) + (a4.z + a4.w)) + ((a5.x + a5.y) + (a5.z + a5.w));
        float t3 = ((a6.x + a6.y) + (a6.z + a6.w)) + ((a7.x + a7.y) + (a7.z + a7.w));
        float sum = (t0 + t1) + (t2 + t3);
        outp[r] = pmv[r] + sa + ofc + __logf(sum);
    }
}

extern "C" void kernel_launch(void* const* d_in, const int* in_sizes, int n_in,
                              void* d_out, int out_size)
{
    const float* X       = (const float*)d_in[0];  // (B,T,D)
    const float* Tm      = (const float*)d_in[1];  // (N,N)
    const float* priors  = (const float*)d_in[2];  // (N,)
    const float* mus     = (const float*)d_in[3];  // (N,D)
    const float* logvars = (const float*)d_in[4];  // (N,D)
    float* outp          = (float*)d_out;          // (B,T)

    float *E, *M, *V, *SA, *Wb, *Zb, *OFF;
    cudaGetSymbolAddress((void**)&E, g_E);
    cudaGetSymbolAddress((void**)&M, g_M);
    cudaGetSymbolAddress((void**)&V, g_V);
    cudaGetSymbolAddress((void**)&SA, g_SA);
    cudaGetSymbolAddress((void**)&Wb, g_Wb);
    cudaGetSymbolAddress((void**)&Zb, g_Zb);
    cudaGetSymbolAddress((void**)&OFF, g_OFF);

    dim3 egrid(T_ / TILE_T, B_);
    emission_kernel<<<egrid, 256>>>(X, mus, logvars);

    dim3 fgrid(B_, CHK / WPB);
    forward_chunk_kernel<<<fgrid, 32 * WPB>>>(Tm, priors, E, V, SA, Wb, Zb);
    splice_kernel<<<B_, 32>>>(Wb, Zb, OFF);
    finalize_kernel<<<B_, 1024>>>(V, M, SA, OFF, outp);
}

// round 17
// speedup vs baseline: 7.8881x; 1.1401x over previous
#include <cuda_runtime.h>
#include <cuda_bf16.h>

#define B_ 64
#define T_ 4096
#define N_ 32
#define D_ 64
#define LOG2PI_F 1.837877066409345f
#define PAD_T 8
#define NSA (T_ / 4)
#define CHK 64            // chunks per batch
#define CL  64            // chunk territory length
#define HWU 16            // warm-up steps (eta^15 ~ 1e-7 mixing)
#define WPB 4             // chunk-warps per block

// Scratch
__device__ float g_E[((size_t)B_ * T_ + PAD_T) * N_];
__device__ float g_M[(size_t)B_ * T_ + PAD_T];
__device__ float g_V[(size_t)B_ * T_ * N_];
__device__ float g_SA[(size_t)B_ * NSA];
__device__ float g_Wb[(size_t)B_ * CHK];
__device__ float g_Zb[(size_t)B_ * CHK];

__device__ __forceinline__ float wmax(float v) {
    #pragma unroll
    for (int o = 16; o; o >>= 1) v = fmaxf(v, __shfl_xor_sync(0xffffffffu, v, o));
    return v;
}
__device__ __forceinline__ float wsum(float v) {
    #pragma unroll
    for (int o = 16; o; o >>= 1) v += __shfl_xor_sync(0xffffffffu, v, o);
    return v;
}

// ---- packed f32x2 helpers ----
__device__ __forceinline__ unsigned long long ffma2(
    unsigned long long a, unsigned long long b, unsigned long long c) {
    unsigned long long d;
    asm("fma.rn.f32x2 %0, %1, %2, %3;" : "=l"(d) : "l"(a), "l"(b), "l"(c));
    return d;
}
__device__ __forceinline__ unsigned long long fadd2(
    unsigned long long a, unsigned long long b) {
    unsigned long long d;
    asm("add.rn.f32x2 %0, %1, %2;" : "=l"(d) : "l"(a), "l"(b));
    return d;
}
__device__ __forceinline__ unsigned long long pack2(float lo, float hi) {
    unsigned long long d;
    asm("mov.b64 %0, {%1, %2};" : "=l"(d) : "f"(lo), "f"(hi));
    return d;
}
__device__ __forceinline__ void unpack2(unsigned long long v, float& lo, float& hi) {
    asm("mov.b64 {%0, %1}, %2;" : "=f"(lo), "=f"(hi) : "l"(v));
}

// ---------------------------------------------------------------------------
// Kernel 1: emissions, register-tiled GEMM style. Block tile = 256t x 32n;
// each thread owns 8t x 4n (t_thr = tid>>3, n_thr = tid&7; n lives in lane
// bits 0-2 so the n-max is 3 shfl_xor). Per d4: 8 LDG.128 (X, L1-resident) +
// 8 LDS.128 (params, broadcast) -> 256 FFMA  (1:16 mem:FMA vs 1:6.4 before).
// ---------------------------------------------------------------------------
#define ET_TILE 256

__global__ void __launch_bounds__(256) emission_kernel(
    const float* __restrict__ X,
    const float* __restrict__ mus,
    const float* __restrict__ logvars)
{
    __shared__ float4 piv[16 * 32];   // [d4][n]: inv-var components
    __shared__ float4 pw [16 * 32];   // [d4][n]: w = -2*mu*iv
    __shared__ float  Kc[32];

    const int tid = threadIdx.x;
    const int b   = blockIdx.y;
    const int t0  = blockIdx.x * ET_TILE;

    float* ivs = reinterpret_cast<float*>(piv);
    float* ws  = reinterpret_cast<float*>(pw);

    for (int idx = tid; idx < N_ * D_; idx += 256) {
        int n = idx >> 6;
        int d = idx & 63;
        float lv = logvars[idx];
        float iv = __expf(-lv);
        int off = ((d >> 2) * 32 + n) * 4 + (d & 3);
        ivs[off] = iv;
        ws[off]  = -2.0f * mus[idx] * iv;
    }
    __syncthreads();

    if (tid < N_) {
        float k = D_ * LOG2PI_F;
        #pragma unroll 8
        for (int d = 0; d < D_; ++d) {
            float mu = mus[tid * D_ + d];
            float iv = ivs[((d >> 2) * 32 + tid) * 4 + (d & 3)];
            k += mu * mu * iv + logvars[tid * D_ + d];
        }
        Kc[tid] = k;
    }
    __syncthreads();

    const int t_thr = tid >> 3;       // 0..31
    const int n_thr = tid & 7;        // 0..7 (lane bits 0-2)
    const int rbase = t_thr * 8;
    const float4* Xv = reinterpret_cast<const float4*>(
        X + ((size_t)b * T_ + t0) * D_);

    float acc[8][4];
    #pragma unroll
    for (int r = 0; r < 8; ++r)
        #pragma unroll
        for (int nn = 0; nn < 4; ++nn) acc[r][nn] = 0.f;

    #pragma unroll
    for (int d4 = 0; d4 < 16; ++d4) {
        float4 iv0 = piv[d4 * 32 + n_thr * 4 + 0];
        float4 iv1 = piv[d4 * 32 + n_thr * 4 + 1];
        float4 iv2 = piv[d4 * 32 + n_thr * 4 + 2];
        float4 iv3 = piv[d4 * 32 + n_thr * 4 + 3];
        float4 w0  = pw [d4 * 32 + n_thr * 4 + 0];
        float4 w1  = pw [d4 * 32 + n_thr * 4 + 1];
        float4 w2  = pw [d4 * 32 + n_thr * 4 + 2];
        float4 w3  = pw [d4 * 32 + n_thr * 4 + 3];
        #pragma unroll
        for (int r = 0; r < 8; ++r) {
            float4 x = Xv[(rbase + r) * 16 + d4];
            float a0 = acc[r][0], a1 = acc[r][1], a2 = acc[r][2], a3 = acc[r][3];
            a0 = fmaf(x.x, fmaf(x.x, iv0.x, w0.x), a0);
            a0 = fmaf(x.y, fmaf(x.y, iv0.y, w0.y), a0);
            a0 = fmaf(x.z, fmaf(x.z, iv0.z, w0.z), a0);
            a0 = fmaf(x.w, fmaf(x.w, iv0.w, w0.w), a0);
            a1 = fmaf(x.x, fmaf(x.x, iv1.x, w1.x), a1);
            a1 = fmaf(x.y, fmaf(x.y, iv1.y, w1.y), a1);
            a1 = fmaf(x.z, fmaf(x.z, iv1.z, w1.z), a1);
            a1 = fmaf(x.w, fmaf(x.w, iv1.w, w1.w), a1);
            a2 = fmaf(x.x, fmaf(x.x, iv2.x, w2.x), a2);
            a2 = fmaf(x.y, fmaf(x.y, iv2.y, w2.y), a2);
            a2 = fmaf(x.z, fmaf(x.z, iv2.z, w2.z), a2);
            a2 = fmaf(x.w, fmaf(x.w, iv2.w, w2.w), a2);
            a3 = fmaf(x.x, fmaf(x.x, iv3.x, w3.x), a3);
            a3 = fmaf(x.y, fmaf(x.y, iv3.y, w3.y), a3);
            a3 = fmaf(x.z, fmaf(x.z, iv3.z, w3.z), a3);
            a3 = fmaf(x.w, fmaf(x.w, iv3.w, w3.w), a3);
            acc[r][0] = a0; acc[r][1] = a1; acc[r][2] = a2; acc[r][3] = a3;
        }
    }

    const float k0 = Kc[n_thr * 4 + 0];
    const float k1 = Kc[n_thr * 4 + 1];
    const float k2 = Kc[n_thr * 4 + 2];
    const float k3 = Kc[n_thr * 4 + 3];
    const unsigned FULL = 0xffffffffu;

    #pragma unroll
    for (int r = 0; r < 8; ++r) {
        float v0 = -0.5f * (acc[r][0] + k0);
        float v1 = -0.5f * (acc[r][1] + k1);
        float v2 = -0.5f * (acc[r][2] + k2);
        float v3 = -0.5f * (acc[r][3] + k3);
        float m = fmaxf(fmaxf(v0, v1), fmaxf(v2, v3));
        m = fmaxf(m, __shfl_xor_sync(FULL, m, 1));
        m = fmaxf(m, __shfl_xor_sync(FULL, m, 2));
        m = fmaxf(m, __shfl_xor_sync(FULL, m, 4));   // max over all 32 n

        const size_t tg = (size_t)b * T_ + t0 + rbase + r;
        float4 e;
        e.x = __expf(v0 - m);
        e.y = __expf(v1 - m);
        e.z = __expf(v2 - m);
        e.w = __expf(v3 - m);
        reinterpret_cast<float4*>(g_E + tg * N_)[n_thr] = e;
        if (n_thr == 0) g_M[tg] = m;
    }
}

// ---------------------------------------------------------------------------
// Kernel 2: CHUNKED forward (unchanged from R15, which passed).
// ---------------------------------------------------------------------------
__global__ void __launch_bounds__(32 * WPB) forward_chunk_kernel(
    const float* __restrict__ Tm,
    const float* __restrict__ priors,
    const float* __restrict__ Eb,
    float* __restrict__ V,
    float* __restrict__ SA,
    float* __restrict__ Wb,
    float* __restrict__ Zb)
{
    __shared__ __align__(16) float ubuf[WPB][2][N_];

    const int b  = blockIdx.x;
    const int w  = threadIdx.x >> 5;
    const int c  = blockIdx.y * WPB + w;
    const int j  = threadIdx.x & 31;

    float Acol[N_];
    #pragma unroll
    for (int i = 0; i < N_; ++i) {
        float raw = Tm[i * N_ + j];
        float mx  = wmax(raw);
        float e   = __expf(raw - mx);
        float s   = wsum(e);
        Acol[i]   = e * __frcp_rn(s);
    }
    unsigned long long A2[N_ / 2];
    #pragma unroll
    for (int p = 0; p < N_ / 2; ++p) A2[p] = pack2(Acol[2 * p], Acol[2 * p + 1]);

    float p  = priors[j];
    float pm = wmax(p);
    float pe = __expf(p - pm);
    float ps = wsum(pe);
    float pi = pe * __frcp_rn(ps);

    const float* Ep = Eb + (size_t)b * T_ * N_ + j;
    float* Vp  = V + (size_t)b * T_ * N_ + j;
    float* SAp = SA + (size_t)b * NSA;

    const int terr   = c * CL;
    const int tinit  = (c == 0) ? 0 : terr - HWU;
    const int tend   = terr + CL;

    float u;
    if (c == 0) {
        u = pi * Ep[0];
        Vp[0] = u;
        if (j == 0) SAp[0] = 0.f;
    } else {
        u = Ep[(size_t)tinit * N_];
    }
    float S = 0.f;
    float r_cur = 1.0f, l_cur = 0.0f;

    float er_cur = Ep[(size_t)(tinit + 1) * N_];
    float e_q1   = Ep[(size_t)(tinit + 2) * N_];
    float e_q2   = Ep[(size_t)(tinit + 3) * N_];
    float e_q3   = Ep[(size_t)(tinit + 4) * N_];

    for (int t = tinit + 1; t < tend; ++t) {
        float e_new = Ep[(size_t)(t + 4) * N_];

        const int buf = t & 1;
        ubuf[w][buf][j] = u;
        __syncwarp();
        const ulonglong2* uv = reinterpret_cast<const ulonglong2*>(ubuf[w][buf]);
        ulonglong2 q0 = uv[0], q1 = uv[1], q2 = uv[2], q3 = uv[3];
        ulonglong2 q4 = uv[4], q5 = uv[5], q6 = uv[6], q7 = uv[7];

        unsigned long long c0, c1, c2, c3;
        c0 = ffma2(q0.x, A2[0], ffma2(q0.y, A2[1], 0ull));
        c1 = ffma2(q1.x, A2[2], ffma2(q1.y, A2[3], 0ull));
        c2 = ffma2(q2.x, A2[4], ffma2(q2.y, A2[5], 0ull));
        c3 = ffma2(q3.x, A2[6], ffma2(q3.y, A2[7], 0ull));
        c0 = ffma2(q4.x, A2[8],  ffma2(q4.y, A2[9],  c0));
        c1 = ffma2(q5.x, A2[10], ffma2(q5.y, A2[11], c1));
        c2 = ffma2(q6.x, A2[12], ffma2(q6.y, A2[13], c2));
        c3 = ffma2(q7.x, A2[14], ffma2(q7.y, A2[15], c3));
        unsigned long long cs = fadd2(fadd2(c0, c1), fadd2(c2, c3));
        float clo, chi;
        unpack2(cs, clo, chi);
        float un = er_cur * (clo + chi);

        if ((t & 3) == 1) {
            unsigned long long s0 = fadd2(fadd2(q0.x, q0.y), fadd2(q1.x, q1.y));
            unsigned long long s1 = fadd2(fadd2(q2.x, q2.y), fadd2(q3.x, q3.y));
            unsigned long long s2 = fadd2(fadd2(q4.x, q4.y), fadd2(q5.x, q5.y));
            unsigned long long s3 = fadd2(fadd2(q6.x, q6.y), fadd2(q7.x, q7.y));
            unsigned long long ss = fadd2(fadd2(s0, s1), fadd2(s2, s3));
            float slo, shi;
            unpack2(ss, slo, shi);
            float sig = slo + shi;
            r_cur = __frcp_rn(sig);
            l_cur = __logf(sig);
        }
        if ((t & 3) == 0) {
            un *= r_cur;
            S += l_cur;
            if (j == 0 && t >= terr) SAp[t >> 2] = S;
        }

        if (t >= terr) Vp[(size_t)t * N_] = un;

        if (t == terr - 1) {
            float sg = wsum(un);
            if (j == 0) Wb[b * CHK + c] = S + __logf(sg);
        }
        if (t == tend - 1) {
            float sg = wsum(un);
            if (j == 0) Zb[b * CHK + c] = S + __logf(sg);
        }

        u = un;
        er_cur = e_q1; e_q1 = e_q2; e_q2 = e_q3; e_q3 = e_new;
    }
}

// ---------------------------------------------------------------------------
// Kernel 3: finalize with FUSED splice. Warp 0 pair-scans the 64 chunk
// boundary corrections into smem; then
// out[b,t] = prefixM[b,t] + SA[b,t/4] + offs[t/CL] + log(sum_n V_t[n]).
// ---------------------------------------------------------------------------
__global__ void __launch_bounds__(1024) finalize_kernel(
    const float* __restrict__ V,
    const float* __restrict__ M,
    const float* __restrict__ SA,
    const float* __restrict__ Wb,
    const float* __restrict__ Zb,
    float* __restrict__ out)
{
    __shared__ float wsums[32];
    __shared__ float offs[CHK];
    const unsigned FULL = 0xffffffffu;
    const int b    = blockIdx.x;
    const int tid  = threadIdx.x;
    const int lane = tid & 31;
    const int wid  = tid >> 5;

    // ---- splice scan (warp 0): offs[c] = sum_{k<=c} (Z[k-1] - W[k])
    if (wid == 0) {
        int c0 = 2 * lane, c1 = 2 * lane + 1;
        float d0 = (c0 >= 1) ? (Zb[b * CHK + c0 - 1] - Wb[b * CHK + c0]) : 0.f;
        float d1 = Zb[b * CHK + c1 - 1] - Wb[b * CHK + c1];
        float s = d0 + d1;
        float sc2 = s;
        #pragma unroll
        for (int o = 1; o < 32; o <<= 1) {
            float v = __shfl_up_sync(FULL, sc2, o);
            if (lane >= o) sc2 += v;
        }
        float excl = sc2 - s;
        offs[c0] = excl + d0;
        offs[c1] = excl + d0 + d1;
    }

    // ---- prefix scan of M
    float4 m4 = reinterpret_cast<const float4*>(M + (size_t)b * T_)[tid];
    float s0 = m4.x;
    float s1 = s0 + m4.y;
    float s2 = s1 + m4.z;
    float s3 = s2 + m4.w;

    float sc = s3;
    #pragma unroll
    for (int o = 1; o < 32; o <<= 1) {
        float v = __shfl_up_sync(FULL, sc, o);
        if (lane >= o) sc += v;
    }
    if (lane == 31) wsums[wid] = sc;
    __syncthreads();
    if (wid == 0) {
        float w = wsums[lane];
        #pragma unroll
        for (int o = 1; o < 32; o <<= 1) {
            float v = __shfl_up_sync(FULL, w, o);
            if (lane >= o) w += v;
        }
        wsums[lane] = w;
    }
    __syncthreads();
    float base = (wid > 0 ? wsums[wid - 1] : 0.f) + (sc - s3);

    const float sa  = SA[(size_t)b * NSA + tid];
    const float ofc = offs[tid / (CL / 4)];
    const float4* Vb = reinterpret_cast<const float4*>(
        V + ((size_t)b * T_ + 4 * (size_t)tid) * N_);
    float* outp = out + (size_t)b * T_ + 4 * tid;

    float pmv[4] = {base + s0, base + s1, base + s2, base + s3};
    #pragma unroll
    for (int r = 0; r < 4; ++r) {
        float4 a0 = Vb[r * 8 + 0], a1 = Vb[r * 8 + 1];
        float4 a2 = Vb[r * 8 + 2], a3 = Vb[r * 8 + 3];
        float4 a4 = Vb[r * 8 + 4], a5 = Vb[r * 8 + 5];
        float4 a6 = Vb[r * 8 + 6], a7 = Vb[r * 8 + 7];
        float t0 = ((a0.x + a0.y) + (a0.z + a0.w)) + ((a1.x + a1.y) + (a1.z + a1.w));
        float t1 = ((a2.x + a2.y) + (a2.z + a2.w)) + ((a3.x + a3.y) + (a3.z + a3.w));
        float t2 = ((a4.x + a4.y) + (a4.z + a4.w)) + ((a5.x + a5.y) + (a5.z + a5.w));
        float t3 = ((a6.x + a6.y) + (a6.z + a6.w)) + ((a7.x + a7.y) + (a7.z + a7.w));
        float sum = (t0 + t1) + (t2 + t3);
        outp[r] = pmv[r] + sa + ofc + __logf(sum);
    }
}

extern "C" void kernel_launch(void* const* d_in, const int* in_sizes, int n_in,
                              void* d_out, int out_size)
{
    const float* X       = (const float*)d_in[0];  // (B,T,D)
    const float* Tm      = (const float*)d_in[1];  // (N,N)
    const float* priors  = (const float*)d_in[2];  // (N,)
    const float* mus     = (const float*)d_in[3];  // (N,D)
    const float* logvars = (const float*)d_in[4];  // (N,D)
    float* outp          = (float*)d_out;          // (B,T)

    float *E, *M, *V, *SA, *Wb, *Zb;
    cudaGetSymbolAddress((void**)&E, g_E);
    cudaGetSymbolAddress((void**)&M, g_M);
    cudaGetSymbolAddress((void**)&V, g_V);
    cudaGetSymbolAddress((void**)&SA, g_SA);
    cudaGetSymbolAddress((void**)&Wb, g_Wb);
    cudaGetSymbolAddress((void**)&Zb, g_Zb);

    dim3 egrid(T_ / ET_TILE, B_);
    emission_kernel<<<egrid, 256>>>(X, mus, logvars);

    dim3 fgrid(B_, CHK / WPB);
    forward_chunk_kernel<<<fgrid, 32 * WPB>>>(Tm, priors, E, V, SA, Wb, Zb);
    finalize_kernel<<<B_, 1024>>>(V, M, SA, Wb, Zb, outp);
}